// round 6
// baseline (speedup 1.0000x reference)
#include <cuda_runtime.h>
#include <cuda_bf16.h>
#include <math.h>
#include <stdint.h>

#define Dm 128
#define TS 132
#define NCH 64
#define CPB 32
#define LN_EPS 1e-5f
#define ATT_EPS 1e-6f
typedef unsigned long long ull;

#if defined(__CUDA_ARCH_FEAT_SM103_ALL) || defined(__CUDA_ARCH_FEAT_SM100_ALL)
#define HAS_TCGEN05 1
#else
#define HAS_TCGEN05 0
#endif

// ---- fp32 scratch in gmem ----
__device__ float g_Qp[NCH * 16384];
__device__ float g_Kp[NCH * 16384];
__device__ float g_Vg[NCH * 16384];
__device__ float g_U [NCH * 16384];
__device__ float g_S [NCH * 16384];
__device__ float g_uv[NCH * Dm];
__device__ float g_sv[NCH * Dm];

// ================= common helpers =================
static __device__ __forceinline__ uint32_t smem_u32(const void* p) {
    uint32_t a;
    asm("{ .reg .u64 t; cvta.to.shared.u64 t, %1; cvt.u32.u64 %0, t; }" : "=r"(a) : "l"(p));
    return a;
}
__device__ __forceinline__ float phi_f(float x) { return x > 0.f ? x + 1.f : expf(x); }
__device__ __forceinline__ float sigmoid_f(float x) { return 1.f / (1.f + expf(-x)); }

template<int R>
__device__ __forceinline__ void ldtile(const float* __restrict__ g, float* __restrict__ s) {
    int tid = threadIdx.x;
    const float4* g4 = (const float4*)g;
#pragma unroll
    for (int i = 0; i < (R * 32) / 256; i++) {
        int idx = tid + i * 256;
        int r = idx >> 5, c = (idx & 31) * 4;
        *(float4*)&s[r * TS + c] = g4[idx];
    }
}

// ---- f32x2 packed helpers (fallback path) ----
__device__ __forceinline__ ull pack2(float lo, float hi) {
    ull r; asm("mov.b64 %0, {%1,%2};" : "=l"(r) : "f"(lo), "f"(hi)); return r;
}
__device__ __forceinline__ void ffma2(ull& d, ull a, ull b) {
    asm("fma.rn.f32x2 %0, %1, %2, %0;" : "+l"(d) : "l"(a), "l"(b));
}
__device__ __forceinline__ float2 unp2(ull v) {
    float2 r; asm("mov.b64 {%0,%1}, %2;" : "=f"(r.x), "=f"(r.y) : "l"(v)); return r;
}
__device__ __forceinline__ void mmz8(ull acc[8][4]) {
#pragma unroll
    for (int i = 0; i < 8; i++)
#pragma unroll
        for (int p = 0; p < 4; p++) acc[i][p] = 0ull;
}
__device__ __forceinline__ void unp8(ull acc[8][4], float f[8][8]) {
#pragma unroll
    for (int i = 0; i < 8; i++)
#pragma unroll
        for (int p = 0; p < 4; p++) {
            float2 v = unp2(acc[i][p]);
            f[i][p * 2] = v.x; f[i][p * 2 + 1] = v.y;
        }
}
__device__ __forceinline__ void mm128p(const float* __restrict__ A, const float* __restrict__ B,
                                       ull acc[8][4], int tr, int tc) {
#pragma unroll 1
    for (int k0 = 0; k0 < 128; k0 += 4) {
        float areg[4][8];
#pragma unroll
        for (int i = 0; i < 8; i++) {
            float4 av = *(const float4*)&A[(tr + i) * TS + k0];
            areg[0][i] = av.x; areg[1][i] = av.y; areg[2][i] = av.z; areg[3][i] = av.w;
        }
#pragma unroll
        for (int kk = 0; kk < 4; kk++) {
            const float* brow = &B[(k0 + kk) * TS + tc];
            float4 b0 = *(const float4*)brow;
            float4 b1 = *(const float4*)(brow + 64);
            ull bp0 = pack2(b0.x, b0.y), bp1 = pack2(b0.z, b0.w);
            ull bp2 = pack2(b1.x, b1.y), bp3 = pack2(b1.z, b1.w);
#pragma unroll
            for (int i = 0; i < 8; i++) {
                ull as = pack2(areg[kk][i], areg[kk][i]);
                ffma2(acc[i][0], as, bp0);
                ffma2(acc[i][1], as, bp1);
                ffma2(acc[i][2], as, bp2);
                ffma2(acc[i][3], as, bp3);
            }
        }
    }
}
__device__ __forceinline__ void mm128p_col(const float* __restrict__ A, const float* __restrict__ B,
                                           ull acc[8][4], int tr, int tc) {
#pragma unroll 1
    for (int k0 = 0; k0 < 128; k0 += 4) {
        float areg[4][8];
#pragma unroll
        for (int kk = 0; kk < 4; kk++) {
            float4 a0 = *(const float4*)&A[(k0 + kk) * TS + tr];
            float4 a1 = *(const float4*)&A[(k0 + kk) * TS + tr + 4];
            areg[kk][0] = a0.x; areg[kk][1] = a0.y; areg[kk][2] = a0.z; areg[kk][3] = a0.w;
            areg[kk][4] = a1.x; areg[kk][5] = a1.y; areg[kk][6] = a1.z; areg[kk][7] = a1.w;
        }
#pragma unroll
        for (int kk = 0; kk < 4; kk++) {
            const float* brow = &B[(k0 + kk) * TS + tc];
            float4 b0 = *(const float4*)brow;
            float4 b1 = *(const float4*)(brow + 64);
            ull bp0 = pack2(b0.x, b0.y), bp1 = pack2(b0.z, b0.w);
            ull bp2 = pack2(b1.x, b1.y), bp3 = pack2(b1.z, b1.w);
#pragma unroll
            for (int i = 0; i < 8; i++) {
                ull as = pack2(areg[kk][i], areg[kk][i]);
                ffma2(acc[i][0], as, bp0);
                ffma2(acc[i][1], as, bp1);
                ffma2(acc[i][2], as, bp2);
                ffma2(acc[i][3], as, bp3);
            }
        }
    }
}

// ================= tcgen05 plumbing =================
static __device__ __forceinline__ bool elect1() {
    uint32_t p;
    asm volatile("{ .reg .pred p; elect.sync _|p, 0xFFFFFFFF; selp.b32 %0, 1, 0, p; }" : "=r"(p));
    return p != 0;
}
#define IDESC_F16 ((1u<<4)|(1u<<7)|(1u<<10)|(16u<<17)|(8u<<24))
__device__ __forceinline__ uint64_t mkdesc(uint32_t addr) {
    return ((uint64_t)2 << 61) | ((uint64_t)1 << 46) | ((uint64_t)64 << 32) | ((uint64_t)1 << 16)
         | ((uint64_t)(addr >> 4) & 0x3FFF);
}
#if HAS_TCGEN05
__device__ __forceinline__ void mma_ss(uint32_t d, uint64_t ad, uint64_t bd, uint32_t en) {
    asm volatile("{\n\t.reg .pred p;\n\tsetp.ne.u32 p, %4, 0;\n\t"
        "tcgen05.mma.cta_group::1.kind::f16 [%0], %1, %2, %3, {%5,%5,%5,%5}, p;\n\t}"
        :: "r"(d), "l"(ad), "l"(bd), "r"(IDESC_F16), "r"(en), "r"(0u) : "memory");
}
__device__ __forceinline__ void mma_tile3(uint32_t d, uint32_t a_addr, uint32_t b_addr,
                                          uint32_t mbar, bool fresh) {
    if (elect1()) {
        uint64_t adb = mkdesc(a_addr), bdb = mkdesc(b_addr);
#pragma unroll
        for (int t = 0; t < 3; t++) {
            uint64_t ao = adb + (t == 2 ? 2048 : 0);
            uint64_t bo = bdb + (t == 1 ? 2048 : 0);
#pragma unroll
            for (int s = 0; s < 8; s++) {
                uint64_t off = (uint64_t)((s >> 2) * 1024 + (s & 3) * 2);
                mma_ss(d, ao + off, bo + off, (t == 0 && s == 0 && fresh) ? 0u : 1u);
            }
        }
        asm volatile("tcgen05.commit.cta_group::1.mbarrier::arrive::one.shared::cluster.b64 [%0];"
                     :: "r"(mbar) : "memory");
    }
}
#define MBAR_INIT(a, c) asm volatile("mbarrier.init.shared.b64 [%0], %1;" :: "r"(a), "r"(c) : "memory")
#define MBAR_INVAL(a)   asm volatile("mbarrier.inval.shared.b64 [%0];" :: "r"(a) : "memory")
#define MBAR_WAIT(a, par) do { uint32_t _m=(a), _p=(par); \
    asm volatile("{\n\t.reg .pred P1;\n\tWL%=:\n\t" \
        "mbarrier.try_wait.parity.acquire.cta.shared::cta.b64 P1, [%0], %1, 0x989680;\n\t" \
        "@P1 bra.uni WD%=;\n\tbra.uni WL%=;\n\tWD%=:\n\t}" :: "r"(_m), "r"(_p) : "memory"); } while(0)
#define TC_ALLOC(a, n)   asm volatile("tcgen05.alloc.cta_group::1.sync.aligned.shared::cta.b32 [%0], %1;" :: "r"(a), "r"(n) : "memory")
#define TC_DEALLOC(t, n) asm volatile("tcgen05.dealloc.cta_group::1.sync.aligned.b32 %0, %1;" :: "r"(t), "r"(n))
#define TC_FENCE_AFTER()  asm volatile("tcgen05.fence::after_thread_sync;" ::: "memory")
#define TC_FENCE_BEFORE() asm volatile("tcgen05.fence::before_thread_sync;" ::: "memory")
#define FENCE_ASYNC()    asm volatile("fence.proxy.async.shared::cta;" ::: "memory")
#define TC_WAIT_LD()     asm volatile("tcgen05.wait::ld.sync.aligned;" ::: "memory")
#define LDTM32(r, addr) \
    asm volatile("tcgen05.ld.sync.aligned.32x32b.x32.b32 " \
        "{%0,%1,%2,%3,%4,%5,%6,%7,%8,%9,%10,%11,%12,%13,%14,%15," \
        "%16,%17,%18,%19,%20,%21,%22,%23,%24,%25,%26,%27,%28,%29,%30,%31}, [%32];" \
        : "=r"((r)[0]),"=r"((r)[1]),"=r"((r)[2]),"=r"((r)[3]),"=r"((r)[4]),"=r"((r)[5]),"=r"((r)[6]),"=r"((r)[7]), \
          "=r"((r)[8]),"=r"((r)[9]),"=r"((r)[10]),"=r"((r)[11]),"=r"((r)[12]),"=r"((r)[13]),"=r"((r)[14]),"=r"((r)[15]), \
          "=r"((r)[16]),"=r"((r)[17]),"=r"((r)[18]),"=r"((r)[19]),"=r"((r)[20]),"=r"((r)[21]),"=r"((r)[22]),"=r"((r)[23]), \
          "=r"((r)[24]),"=r"((r)[25]),"=r"((r)[26]),"=r"((r)[27]),"=r"((r)[28]),"=r"((r)[29]),"=r"((r)[30]),"=r"((r)[31]) \
        : "r"(addr))
#endif

// bf16 (row,col) byte offset in 128x128 K-major SW128 blocked-atom tile
__device__ __forceinline__ uint32_t bfoff(int row, int col) {
    uint32_t u = (uint32_t)(((row >> 3) + (col >> 6) * 16) * 1024 + (row & 7) * 128 + (col & 63) * 2);
    return u ^ ((u >> 3) & 0x70);
}
__device__ __forceinline__ uint32_t packbf(float a, float b) {
    __nv_bfloat16 ha = __float2bfloat16(a), hb = __float2bfloat16(b);
    return (uint32_t)__bfloat16_as_ushort(ha) | ((uint32_t)__bfloat16_as_ushort(hb) << 16);
}
__device__ __forceinline__ void fill_pair(uint32_t* __restrict__ dst, const float* __restrict__ g,
                                          int ld, bool trans) {
    int tid = threadIdx.x;
    if (!trans) {
#pragma unroll 4
        for (int it = 0; it < 32; it++) {
            int p = tid + it * 256;
            int r = p >> 6, c = (p & 63) * 2;
            float2 v = *(const float2*)&g[r * ld + c];
            float h0 = __bfloat162float(__float2bfloat16(v.x));
            float h1 = __bfloat162float(__float2bfloat16(v.y));
            uint32_t w = bfoff(r, c) >> 2;
            dst[w] = packbf(v.x, v.y);
            dst[8192 + w] = packbf(v.x - h0, v.y - h1);
        }
    } else {
        __nv_bfloat16* d16 = (__nv_bfloat16*)dst;
#pragma unroll 4
        for (int it = 0; it < 64; it++) {
            int e = tid + it * 256;
            int r = e >> 7, c = e & 127;
            float f = g[r * ld + c];
            __nv_bfloat16 h = __float2bfloat16(f);
            __nv_bfloat16 l = __float2bfloat16(f - __bfloat162float(h));
            uint32_t u = bfoff(c, r) >> 1;
            d16[u] = h;
            d16[u + 16384] = l;
        }
    }
}
__device__ __forceinline__ void stage_out(float* __restrict__ g, const float* __restrict__ stage) {
    int tid = threadIdx.x;
#pragma unroll
    for (int it = 0; it < 16; it++) {
        int p = tid + it * 256;
        int r = p >> 5, c = (p & 31) * 4;
        *(float4*)&g[r * 128 + c] = *(const float4*)&stage[r * TS + c];
    }
}
__device__ __forceinline__ void ln_chunk(const float* __restrict__ tok, float* __restrict__ buf,
                                         const float* __restrict__ g1, const float* __restrict__ b1) {
    int lane = threadIdx.x & 31, wid = threadIdx.x >> 5;
    float4 gg = ((const float4*)g1)[lane], bb = ((const float4*)b1)[lane];
    for (int r = wid; r < 128; r += 8) {
        float4 v = ((const float4*)(tok + r * 128))[lane];
        float s = v.x + v.y + v.z + v.w;
        float ss = v.x * v.x + v.y * v.y + v.z * v.z + v.w * v.w;
#pragma unroll
        for (int o = 16; o; o >>= 1) {
            s  += __shfl_xor_sync(0xffffffffu, s,  o);
            ss += __shfl_xor_sync(0xffffffffu, ss, o);
        }
        float mu = s * (1.f / 128.f);
        float inv = rsqrtf(ss * (1.f / 128.f) - mu * mu + LN_EPS);
        float* d = &buf[r * TS + lane * 4];
        d[0] = (v.x - mu) * inv * gg.x + bb.x;
        d[1] = (v.y - mu) * inv * gg.y + bb.y;
        d[2] = (v.z - mu) * inv * gg.z + bb.z;
        d[3] = (v.w - mu) * inv * gg.w + bb.w;
    }
}

// smem: S1 (64KB) | S2 (64KB) | stage (128*132*4 = 67584) | aux (2112)
#define STAGE_OFF 131072
#define AUX_OFF   (131072 + 128 * TS * 4)
#define SMEMSZ    (AUX_OFF + 2112)

// ================= k_front =================
__global__ void __launch_bounds__(256) k_front(const float* __restrict__ tokens,
        const float* __restrict__ Wq, const float* __restrict__ Wk,
        const float* __restrict__ Wv, const float* __restrict__ Wg,
        const float* __restrict__ bg, const float* __restrict__ g1,
        const float* __restrict__ b1) {
    extern __shared__ __align__(1024) char smem[];
    int tid = threadIdx.x, wid = tid >> 5, ci = blockIdx.x;
    const float* tok = tokens + (size_t)ci * 16384;
#if HAS_TCGEN05
    uint32_t* S1 = (uint32_t*)smem;
    uint32_t* S2 = (uint32_t*)(smem + 65536);
    float* stage = (float*)(smem + STAGE_OFF);
    char* aux = smem + AUX_OFF;
    uint32_t auxa = smem_u32(aux), mbar = auxa + 8;

    if (wid == 0) TC_ALLOC(auxa, 256);
    if (tid == 0) MBAR_INIT(mbar, 1);
    __syncthreads();
    uint32_t tmem;
    asm volatile("ld.shared.b32 %0,[%1];" : "=r"(tmem) : "r"(auxa));
    uint32_t D0 = tmem, D1 = tmem + 128;
    uint32_t uS1 = smem_u32(S1), uS2 = smem_u32(S2);
    int ph = 0;

    ln_chunk(tok, stage, g1, b1);
    __syncthreads();
    fill_pair(S1, stage, TS, false);      // X
    fill_pair(S2, Wq, 128, true);         // Wq^T
    FENCE_ASYNC();
    __syncthreads();
    if (wid == 0) mma_tile3(D0, uS1, uS2, mbar, true);            // Q
    MBAR_WAIT(mbar, ph); ph ^= 1; TC_FENCE_AFTER();
    fill_pair(S2, Wk, 128, true);
    FENCE_ASYNC();
    __syncthreads();
    if (wid == 0) mma_tile3(D1, uS1, uS2, mbar, true);            // K
    if (tid < 128) {                                              // Qp epilogue
#pragma unroll
        for (int blk = 0; blk < 4; blk++) {
            uint32_t r[32];
            LDTM32(r, D0 + blk * 32); TC_WAIT_LD();
#pragma unroll
            for (int j = 0; j < 32; j++)
                stage[tid * TS + blk * 32 + j] = phi_f(__uint_as_float(r[j]));
        }
    }
    __syncthreads();
    stage_out(g_Qp + (size_t)ci * 16384, stage);
    MBAR_WAIT(mbar, ph); ph ^= 1; TC_FENCE_AFTER();
    __syncthreads();
    fill_pair(S2, Wv, 128, true);
    FENCE_ASYNC(); TC_FENCE_BEFORE();
    __syncthreads();
    if (wid == 0) mma_tile3(D0, uS1, uS2, mbar, true);            // V
    if (tid < 128) {                                              // Kp epilogue
#pragma unroll
        for (int blk = 0; blk < 4; blk++) {
            uint32_t r[32];
            LDTM32(r, D1 + blk * 32); TC_WAIT_LD();
#pragma unroll
            for (int j = 0; j < 32; j++)
                stage[tid * TS + blk * 32 + j] = phi_f(__uint_as_float(r[j]));
        }
    }
    __syncthreads();
    stage_out(g_Kp + (size_t)ci * 16384, stage);
    if (tid < 128) {
        float s = 0.f;
        for (int t = 0; t < 128; t++) s += stage[t * TS + tid];
        g_uv[ci * Dm + tid] = s;
    }
    MBAR_WAIT(mbar, ph); ph ^= 1; TC_FENCE_AFTER();               // V done
    __syncthreads();
    fill_pair(S2, Wg, 128, true);
    FENCE_ASYNC(); TC_FENCE_BEFORE();
    __syncthreads();
    if (wid == 0) mma_tile3(D1, uS1, uS2, mbar, true);            // G
    MBAR_WAIT(mbar, ph); ph ^= 1; TC_FENCE_AFTER();
    fill_pair(S1, stage, TS, true);                               // Kp^T (stage holds Kp)
    __syncthreads();
    if (tid < 128) {                                              // Vg epilogue
#pragma unroll
        for (int blk = 0; blk < 4; blk++) {
            uint32_t rv[32], rg[32];
            LDTM32(rv, D0 + blk * 32); TC_WAIT_LD();
            LDTM32(rg, D1 + blk * 32); TC_WAIT_LD();
#pragma unroll
            for (int j = 0; j < 32; j++) {
                int c = blk * 32 + j;
                stage[tid * TS + c] = __uint_as_float(rv[j]) *
                                      sigmoid_f(__uint_as_float(rg[j]) + bg[c]);
            }
        }
    }
    __syncthreads();
    stage_out(g_Vg + (size_t)ci * 16384, stage);
    fill_pair(S2, stage, TS, true);                               // Vg^T
    FENCE_ASYNC(); TC_FENCE_BEFORE();
    __syncthreads();
    if (wid == 0) mma_tile3(D0, uS1, uS2, mbar, true);            // U = Kp^T Vg
    MBAR_WAIT(mbar, ph); ph ^= 1; TC_FENCE_AFTER();
    if (tid < 128) {
#pragma unroll
        for (int blk = 0; blk < 4; blk++) {
            uint32_t r[32];
            LDTM32(r, D0 + blk * 32); TC_WAIT_LD();
#pragma unroll
            for (int j = 0; j < 32; j++)
                stage[tid * TS + blk * 32 + j] = __uint_as_float(r[j]);
        }
    }
    __syncthreads();
    stage_out(g_U + (size_t)ci * 16384, stage);
    __syncthreads();
    if (tid == 0) MBAR_INVAL(mbar);
    __syncthreads();
    if (wid == 0) TC_DEALLOC(tmem, 256);
#else
    // -------- fallback: FFMA2 SIMT --------
    float* X   = (float*)smem;
    float* W   = X + 128 * TS;
    float* stg = (float*)(smem + STAGE_OFF);
    int tr = (tid >> 4) * 8, tc = (tid & 15) * 4;
    ull acc[8][4]; float f[8][8];

    ln_chunk(tok, X, g1, b1);
    __syncthreads();
    ldtile<128>(Wq, W); __syncthreads();
    mmz8(acc); mm128p(X, W, acc, tr, tc); unp8(acc, f);
#pragma unroll
    for (int i = 0; i < 8; i++) {
        float* d = g_Qp + (size_t)ci * 16384 + (tr + i) * 128;
        *(float4*)&d[tc]      = make_float4(phi_f(f[i][0]), phi_f(f[i][1]), phi_f(f[i][2]), phi_f(f[i][3]));
        *(float4*)&d[tc + 64] = make_float4(phi_f(f[i][4]), phi_f(f[i][5]), phi_f(f[i][6]), phi_f(f[i][7]));
    }
    __syncthreads();
    ldtile<128>(Wk, W); __syncthreads();
    mmz8(acc); mm128p(X, W, acc, tr, tc); unp8(acc, f);
#pragma unroll
    for (int i = 0; i < 8; i++) {
        float4 lo = make_float4(phi_f(f[i][0]), phi_f(f[i][1]), phi_f(f[i][2]), phi_f(f[i][3]));
        float4 hi = make_float4(phi_f(f[i][4]), phi_f(f[i][5]), phi_f(f[i][6]), phi_f(f[i][7]));
        float* d = g_Kp + (size_t)ci * 16384 + (tr + i) * 128;
        *(float4*)&d[tc] = lo; *(float4*)&d[tc + 64] = hi;
        *(float4*)&stg[(tr + i) * TS + tc] = lo; *(float4*)&stg[(tr + i) * TS + tc + 64] = hi;
    }
    __syncthreads();
    if (tid < 128) {
        float s = 0.f;
        for (int t = 0; t < 128; t++) s += stg[t * TS + tid];
        g_uv[ci * Dm + tid] = s;
    }
    ldtile<128>(Wv, W); __syncthreads();
    mmz8(acc); mm128p(X, W, acc, tr, tc); unp8(acc, f);
#pragma unroll
    for (int i = 0; i < 8; i++) {
        float* d = g_Vg + (size_t)ci * 16384 + (tr + i) * 128;
        *(float4*)&d[tc]      = make_float4(f[i][0], f[i][1], f[i][2], f[i][3]);
        *(float4*)&d[tc + 64] = make_float4(f[i][4], f[i][5], f[i][6], f[i][7]);
    }
    __syncthreads();
    ldtile<128>(Wg, W); __syncthreads();
    mmz8(acc); mm128p(X, W, acc, tr, tc); unp8(acc, f);
    __syncthreads();
#pragma unroll
    for (int i = 0; i < 8; i++) {
        float* d = g_Vg + (size_t)ci * 16384 + (tr + i) * 128;
        float4 v0 = *(float4*)&d[tc], v1 = *(float4*)&d[tc + 64];
        float4 o0 = make_float4(v0.x * sigmoid_f(f[i][0] + bg[tc]),
                                v0.y * sigmoid_f(f[i][1] + bg[tc + 1]),
                                v0.z * sigmoid_f(f[i][2] + bg[tc + 2]),
                                v0.w * sigmoid_f(f[i][3] + bg[tc + 3]));
        float4 o1 = make_float4(v1.x * sigmoid_f(f[i][4] + bg[tc + 64]),
                                v1.y * sigmoid_f(f[i][5] + bg[tc + 65]),
                                v1.z * sigmoid_f(f[i][6] + bg[tc + 66]),
                                v1.w * sigmoid_f(f[i][7] + bg[tc + 67]));
        *(float4*)&d[tc] = o0; *(float4*)&d[tc + 64] = o1;
        *(float4*)&X[(tr + i) * TS + tc] = o0; *(float4*)&X[(tr + i) * TS + tc + 64] = o1;
    }
    __syncthreads();
    mmz8(acc); mm128p_col(stg, X, acc, tr, tc); unp8(acc, f);
#pragma unroll
    for (int i = 0; i < 8; i++) {
        float* d = g_U + (size_t)ci * 16384 + (tr + i) * 128;
        *(float4*)&d[tc]      = make_float4(f[i][0], f[i][1], f[i][2], f[i][3]);
        *(float4*)&d[tc + 64] = make_float4(f[i][4], f[i][5], f[i][6], f[i][7]);
    }
#endif
}

// ================= k_prefix =================
__global__ void k_prefix() {
    int b = blockIdx.y;
    int e = blockIdx.x * blockDim.x + threadIdx.x;
    if (e < Dm * Dm) {
        float acc = 0.f;
        float nxt = g_U[(size_t)(b * CPB) * 16384 + e];
        for (int c = 0; c < CPB; c++) {
            size_t idx = (size_t)(b * CPB + c) * 16384 + e;
            float cur = nxt;
            if (c < CPB - 1) nxt = g_U[idx + 16384];
            g_S[idx] = acc;
            acc += cur;
        }
    } else if (e < Dm * Dm + Dm) {
        int h = e - Dm * Dm;
        float acc = 0.f;
        for (int c = 0; c < CPB; c++) {
            int idx = (b * CPB + c) * Dm + h;
            g_sv[idx] = acc;
            acc += g_uv[idx];
        }
    }
}

// ================= k_attn =================
__global__ void __launch_bounds__(256) k_attn(const float* __restrict__ tokens,
        const float* __restrict__ Wo, const float* __restrict__ g2,
        const float* __restrict__ b2, float* __restrict__ out) {
    extern __shared__ __align__(1024) char smem[];
    int tid = threadIdx.x, lane = tid & 31, wid = tid >> 5, ci = blockIdx.x;
#if HAS_TCGEN05
    uint32_t* S1 = (uint32_t*)smem;
    uint32_t* S2 = (uint32_t*)(smem + 65536);
    float* stage = (float*)(smem + STAGE_OFF);
    char* aux = smem + AUX_OFF;
    uint32_t auxa = smem_u32(aux), mbar = auxa + 8;
    float* svs    = (float*)(aux + 16);
    float* denomv = svs + 128;
    float* mus    = denomv + 128;
    float* invs   = mus + 128;

    if (wid == 0) TC_ALLOC(auxa, 256);
    if (tid == 0) MBAR_INIT(mbar, 1);
    if (tid < 128) svs[tid] = g_sv[ci * Dm + tid];
    __syncthreads();
    uint32_t tmem;
    asm volatile("ld.shared.b32 %0,[%1];" : "=r"(tmem) : "r"(auxa));
    uint32_t D0 = tmem, D1 = tmem + 128;
    uint32_t uS1 = smem_u32(S1), uS2 = smem_u32(S2);
    int ph = 0;

    fill_pair(S1, g_Qp + (size_t)ci * 16384, 128, false);
    fill_pair(S2, g_S  + (size_t)ci * 16384, 128, true);
    FENCE_ASYNC();
    __syncthreads();
    if (wid == 0) mma_tile3(D0, uS1, uS2, mbar, true);      // inter = Qp @ S
    MBAR_WAIT(mbar, ph); ph ^= 1; TC_FENCE_AFTER();
    fill_pair(S2, g_Kp + (size_t)ci * 16384, 128, false);
    FENCE_ASYNC();
    __syncthreads();
    if (wid == 0) mma_tile3(D1, uS1, uS2, mbar, true);      // scores = Qp Kp^T
    MBAR_WAIT(mbar, ph); ph ^= 1; TC_FENCE_AFTER();
    fill_pair(S2, g_Vg + (size_t)ci * 16384, 128, true);
    __syncthreads();
    if (tid < 128) {                                        // mask + denom; Amask -> S1
        int t = tid;
        float den = 0.f;
        const float* qrow = g_Qp + ((size_t)ci * 128 + t) * 128;
        for (int j = 0; j < 128; j++) den += qrow[j] * svs[j];
#pragma unroll
        for (int blk = 0; blk < 4; blk++) {
            uint32_t r[32];
            LDTM32(r, D1 + blk * 32); TC_WAIT_LD();
#pragma unroll
            for (int j = 0; j < 32; j += 2) {
                int c = blk * 32 + j;
                float f0 = __uint_as_float(r[j]);     if (c > t)     f0 = 0.f;
                float f1 = __uint_as_float(r[j + 1]); if (c + 1 > t) f1 = 0.f;
                den += f0 + f1;
                float h0 = __bfloat162float(__float2bfloat16(f0));
                float h1 = __bfloat162float(__float2bfloat16(f1));
                uint32_t w = bfoff(t, c) >> 2;
                S1[w] = packbf(f0, f1);
                S1[8192 + w] = packbf(f0 - h0, f1 - h1);
            }
        }
        denomv[t] = fmaxf(den, ATT_EPS);
    }
    FENCE_ASYNC(); TC_FENCE_BEFORE();
    __syncthreads();
    if (wid == 0) mma_tile3(D0, uS1, uS2, mbar, false);     // D0 += Amask @ Vg
    MBAR_WAIT(mbar, ph); ph ^= 1; TC_FENCE_AFTER();
    if (tid < 128) {
        float inv = 1.f / denomv[tid];
#pragma unroll
        for (int blk = 0; blk < 4; blk++) {
            uint32_t r[32];
            LDTM32(r, D0 + blk * 32); TC_WAIT_LD();
#pragma unroll
            for (int j = 0; j < 32; j++)
                stage[tid * TS + blk * 32 + j] = __uint_as_float(r[j]) * inv;
        }
    }
    __syncthreads();
    fill_pair(S1, stage, TS, false);                        // At
    fill_pair(S2, Wo, 128, true);
    FENCE_ASYNC(); TC_FENCE_BEFORE();
    __syncthreads();
    if (wid == 0) mma_tile3(D1, uS1, uS2, mbar, true);      // At @ Wo
    MBAR_WAIT(mbar, ph); ph ^= 1; TC_FENCE_AFTER();
    if (tid < 128) {
        int t = tid;
        float s = 0.f, ss = 0.f;
        const float* trow = tokens + ((size_t)ci * 128 + t) * 128;
#pragma unroll
        for (int blk = 0; blk < 4; blk++) {
            uint32_t r[32];
            LDTM32(r, D1 + blk * 32); TC_WAIT_LD();
#pragma unroll
            for (int j = 0; j < 32; j++) {
                int c = blk * 32 + j;
                float o = trow[c] + 0.1f * __uint_as_float(r[j]);
                stage[t * TS + c] = o;
                s += o; ss += o * o;
            }
        }
        float mu = s * (1.f / 128.f);
        mus[t] = mu;
        invs[t] = rsqrtf(ss * (1.f / 128.f) - mu * mu + LN_EPS);
    }
    __syncthreads();
#pragma unroll
    for (int it = 0; it < 16; it++) {
        int p = tid + it * 256;
        int r = p >> 5, c4 = p & 31;
        float4 x = *(const float4*)&stage[r * TS + c4 * 4];
        float4 gg = ((const float4*)g2)[c4], bb = ((const float4*)b2)[c4];
        float mu = mus[r], iv = invs[r];
        float4 o4;
        o4.x = (x.x - mu) * iv * gg.x + bb.x;
        o4.y = (x.y - mu) * iv * gg.y + bb.y;
        o4.z = (x.z - mu) * iv * gg.z + bb.z;
        o4.w = (x.w - mu) * iv * gg.w + bb.w;
        *(float4*)&out[((size_t)ci * 128 + r) * 128 + c4 * 4] = o4;
    }
    __syncthreads();
    if (tid == 0) MBAR_INVAL(mbar);
    __syncthreads();
    if (wid == 0) TC_DEALLOC(tmem, 256);
#else
    // -------- fallback --------
    float* bufQ = (float*)smem;
    float* bufW = bufQ + 128 * TS;
    float* bufA = (float*)(smem + STAGE_OFF);
    float* svs    = (float*)(smem + AUX_OFF);
    float* denomv = svs + 128;
    int tr = (tid >> 4) * 8, tc = (tid & 15) * 4;
    ull acc[8][4]; float f[8][8];

    ldtile<128>(g_Qp + (size_t)ci * 16384, bufQ);
    {
        const float* Kc = g_Kp + (size_t)ci * 16384;
#pragma unroll
        for (int it = 0; it < 64; it++) {
            int e = tid + it * 256;
            bufW[(e & 127) * TS + (e >> 7)] = Kc[e];
        }
    }
    if (tid < 128) svs[tid] = g_sv[ci * Dm + tid];
    __syncthreads();
    mmz8(acc); mm128p(bufQ, bufW, acc, tr, tc); unp8(acc, f);
    __syncthreads();
#pragma unroll
    for (int i = 0; i < 8; i++) {
        int t = tr + i;
#pragma unroll
        for (int j = 0; j < 4; j++) {
            if (tc + j > t) f[i][j] = 0.f;
            if (tc + 64 + j > t) f[i][j + 4] = 0.f;
        }
        *(float4*)&bufA[t * TS + tc]      = make_float4(f[i][0], f[i][1], f[i][2], f[i][3]);
        *(float4*)&bufA[t * TS + tc + 64] = make_float4(f[i][4], f[i][5], f[i][6], f[i][7]);
    }
    __syncthreads();
    for (int r = wid; r < 128; r += 8) {
        float s = 0.f;
#pragma unroll
        for (int c4 = 0; c4 < 4; c4++) {
            int c = lane + c4 * 32;
            s += bufA[r * TS + c] + bufQ[r * TS + c] * svs[c];
        }
#pragma unroll
        for (int o = 16; o; o >>= 1) s += __shfl_xor_sync(0xffffffffu, s, o);
        if (lane == 0) denomv[r] = fmaxf(s, ATT_EPS);
    }
    __syncthreads();
    ldtile<128>(g_Vg + (size_t)ci * 16384, bufW);
    __syncthreads();
    mmz8(acc); mm128p(bufA, bufW, acc, tr, tc);
    __syncthreads();
    ldtile<128>(g_S + (size_t)ci * 16384, bufW);
    __syncthreads();
    mm128p(bufQ, bufW, acc, tr, tc); unp8(acc, f);
    __syncthreads();
#pragma unroll
    for (int i = 0; i < 8; i++) {
        float inv = 1.f / denomv[tr + i];
        *(float4*)&bufA[(tr + i) * TS + tc] =
            make_float4(f[i][0] * inv, f[i][1] * inv, f[i][2] * inv, f[i][3] * inv);
        *(float4*)&bufA[(tr + i) * TS + tc + 64] =
            make_float4(f[i][4] * inv, f[i][5] * inv, f[i][6] * inv, f[i][7] * inv);
    }
    __syncthreads();
    ldtile<128>(Wo, bufW);
    __syncthreads();
    mmz8(acc); mm128p(bufA, bufW, acc, tr, tc); unp8(acc, f);
    __syncthreads();
#pragma unroll
    for (int i = 0; i < 8; i++) {
        const float* trow = tokens + ((size_t)ci * 128 + tr + i) * 128;
        float4 t0 = *(const float4*)&trow[tc];
        float4 t1 = *(const float4*)&trow[tc + 64];
        *(float4*)&bufA[(tr + i) * TS + tc] =
            make_float4(t0.x + 0.1f * f[i][0], t0.y + 0.1f * f[i][1],
                        t0.z + 0.1f * f[i][2], t0.w + 0.1f * f[i][3]);
        *(float4*)&bufA[(tr + i) * TS + tc + 64] =
            make_float4(t1.x + 0.1f * f[i][4], t1.y + 0.1f * f[i][5],
                        t1.z + 0.1f * f[i][6], t1.w + 0.1f * f[i][7]);
    }
    __syncthreads();
    {
        float4 gg = ((const float4*)g2)[lane], bb = ((const float4*)b2)[lane];
        for (int r = wid; r < 128; r += 8) {
            float4 v = *(float4*)&bufA[r * TS + lane * 4];
            float s = v.x + v.y + v.z + v.w;
            float ss = v.x * v.x + v.y * v.y + v.z * v.z + v.w * v.w;
#pragma unroll
            for (int o = 16; o; o >>= 1) {
                s  += __shfl_xor_sync(0xffffffffu, s,  o);
                ss += __shfl_xor_sync(0xffffffffu, ss, o);
            }
            float mu = s * (1.f / 128.f);
            float inv = rsqrtf(ss * (1.f / 128.f) - mu * mu + LN_EPS);
            float4 o4;
            o4.x = (v.x - mu) * inv * gg.x + bb.x;
            o4.y = (v.y - mu) * inv * gg.y + bb.y;
            o4.z = (v.z - mu) * inv * gg.z + bb.z;
            o4.w = (v.w - mu) * inv * gg.w + bb.w;
            *(float4*)&out[((size_t)ci * 128 + r) * 128 + lane * 4] = o4;
        }
    }
#endif
}

extern "C" void kernel_launch(void* const* d_in, const int* in_sizes, int n_in,
                              void* d_out, int out_size) {
    const float* tokens = (const float*)d_in[0];
    const float* Wq = (const float*)d_in[1];
    const float* Wk = (const float*)d_in[2];
    const float* Wv = (const float*)d_in[3];
    const float* Wg = (const float*)d_in[4];
    const float* bg = (const float*)d_in[5];
    const float* Wo = (const float*)d_in[6];
    const float* g1 = (const float*)d_in[7];
    const float* b1 = (const float*)d_in[8];
    const float* g2 = (const float*)d_in[9];
    const float* b2 = (const float*)d_in[10];
    float* out = (float*)d_out;

    cudaFuncSetAttribute(k_front, cudaFuncAttributeMaxDynamicSharedMemorySize, SMEMSZ);
    cudaFuncSetAttribute(k_attn,  cudaFuncAttributeMaxDynamicSharedMemorySize, SMEMSZ);

    k_front<<<NCH, 256, SMEMSZ>>>(tokens, Wq, Wk, Wv, Wg, bg, g1, b1);
    k_prefix<<<dim3(65, 2), 256>>>();
    k_attn<<<NCH, 256, SMEMSZ>>>(tokens, Wo, g2, b2, out);
}

// round 7
// speedup vs baseline: 1.7798x; 1.7798x over previous
#include <cuda_runtime.h>
#include <cuda_bf16.h>
#include <math.h>
#include <stdint.h>

#define Dm 128
#define TS 132
#define NCH 64
#define CPB 32
#define LN_EPS 1e-5f
#define ATT_EPS 1e-6f

#if defined(__CUDA_ARCH_FEAT_SM103_ALL) || defined(__CUDA_ARCH_FEAT_SM100_ALL)
#define HAS_TC 1
#else
#define HAS_TC 0
#endif

// pair tiles: u32[16384] = hi plane [0..8191], lo plane [8192..16383]
__device__ uint32_t g_WT  [5 * 16384];     // WqT WkT WvT WgT WoT
__device__ uint32_t g_QpP [NCH * 16384];
__device__ uint32_t g_KpP [NCH * 16384];
__device__ uint32_t g_KpTP[NCH * 16384];
__device__ uint32_t g_VgTP[NCH * 16384];
__device__ uint32_t g_STP [NCH * 16384];
__device__ uint32_t g_AtP [NCH * 16384];
__device__ float g_V [NCH * 16384];
__device__ float g_G [NCH * 16384];
__device__ float g_U [NCH * 16384];
__device__ float g_uv[NCH * Dm];
__device__ float g_sv[NCH * Dm];

// ================= helpers =================
static __device__ __forceinline__ uint32_t smem_u32(const void* p) {
    uint32_t a;
    asm("{ .reg .u64 t; cvta.to.shared.u64 t, %1; cvt.u32.u64 %0, t; }" : "=r"(a) : "l"(p));
    return a;
}
__device__ __forceinline__ float phi_f(float x) { return x > 0.f ? x + 1.f : __expf(x); }
__device__ __forceinline__ float sig_f(float x) { return 1.f / (1.f + __expf(-x)); }

__device__ __forceinline__ uint32_t bfoff(int row, int col) {
    uint32_t u = (uint32_t)(((row >> 3) + (col >> 6) * 16) * 1024 + (row & 7) * 128 + (col & 63) * 2);
    return u ^ ((u >> 3) & 0x70);
}
__device__ __forceinline__ uint32_t packbf(float a, float b) {
    __nv_bfloat16 ha = __float2bfloat16(a), hb = __float2bfloat16(b);
    return (uint32_t)__bfloat16_as_ushort(ha) | ((uint32_t)__bfloat16_as_ushort(hb) << 16);
}
__device__ __forceinline__ void pair2(float a, float b, uint32_t& hi, uint32_t& lo) {
    float ra = __bfloat162float(__float2bfloat16(a));
    float rb = __bfloat162float(__float2bfloat16(b));
    hi = packbf(a, b);
    lo = packbf(a - ra, b - rb);
}
__device__ __forceinline__ float2 unpackbf2(uint32_t u) {
    __nv_bfloat162 v = *reinterpret_cast<__nv_bfloat162*>(&u);
    return __bfloat1622float2(v);
}

// non-transposed pair fill: dst(row=r, k=c) = src[r][c]
template<int NT>
__device__ __forceinline__ void fill_nt(uint32_t* __restrict__ dst, const float* __restrict__ src, int ld) {
    int tid = threadIdx.x;
#pragma unroll
    for (int it = 0; it < 8192 / NT; it++) {
        int p = tid + it * NT;
        int r = p >> 6, c = (p & 63) * 2;
        float2 v = *(const float2*)&src[r * ld + c];
        uint32_t hi, lo; pair2(v.x, v.y, hi, lo);
        uint32_t w = bfoff(r, c) >> 2;
        dst[w] = hi; dst[8192 + w] = lo;
    }
}
// transposed pair fill: dst(row=n, k=k) = src[k][n]
template<int NT>
__device__ __forceinline__ void fill_t(uint32_t* __restrict__ dst, const float* __restrict__ src, int ld) {
    int tid = threadIdx.x;
#pragma unroll
    for (int it = 0; it < 8192 / NT; it++) {
        int p = tid + it * NT;
        int n = p & 127, k = (p >> 7) * 2;
        float f0 = src[k * ld + n];
        float f1 = src[(k + 1) * ld + n];
        uint32_t hi, lo; pair2(f0, f1, hi, lo);
        uint32_t w = bfoff(n, k) >> 2;
        dst[w] = hi; dst[8192 + w] = lo;
    }
}
template<int NT>
__device__ __forceinline__ void cp64k(void* __restrict__ dst, const void* __restrict__ src) {
    float4* d = (float4*)dst; const float4* s = (const float4*)src;
    int tid = threadIdx.x;
#pragma unroll
    for (int it = 0; it < 4096 / NT; it++) d[tid + it * NT] = s[tid + it * NT];
}
template<int NT>
__device__ __forceinline__ void stage_out(float* __restrict__ g, const float* __restrict__ stage) {
    int tid = threadIdx.x;
#pragma unroll
    for (int it = 0; it < 4096 / NT; it++) {
        int p = tid + it * NT;
        int r = p >> 5, c = (p & 31) * 4;
        *(float4*)&g[r * 128 + c] = *(const float4*)&stage[r * TS + c];
    }
}
// LN of one 128-row chunk into buf (stride TS), 512 threads (16 warps)
__device__ __forceinline__ void ln512(const float* __restrict__ tok, float* __restrict__ buf,
                                      const float* __restrict__ g1, const float* __restrict__ b1) {
    int lane = threadIdx.x & 31, wid = threadIdx.x >> 5;
    float4 gg = ((const float4*)g1)[lane], bb = ((const float4*)b1)[lane];
    for (int r = wid; r < 128; r += 16) {
        float4 v = ((const float4*)(tok + r * 128))[lane];
        float s = v.x + v.y + v.z + v.w;
        float ss = v.x * v.x + v.y * v.y + v.z * v.z + v.w * v.w;
#pragma unroll
        for (int o = 16; o; o >>= 1) {
            s  += __shfl_xor_sync(0xffffffffu, s,  o);
            ss += __shfl_xor_sync(0xffffffffu, ss, o);
        }
        float mu = s * (1.f / 128.f);
        float inv = rsqrtf(ss * (1.f / 128.f) - mu * mu + LN_EPS);
        float* d = &buf[r * TS + lane * 4];
        d[0] = (v.x - mu) * inv * gg.x + bb.x;
        d[1] = (v.y - mu) * inv * gg.y + bb.y;
        d[2] = (v.z - mu) * inv * gg.z + bb.z;
        d[3] = (v.w - mu) * inv * gg.w + bb.w;
    }
}

// ================= tcgen05 plumbing (proven in R6) =================
static __device__ __forceinline__ bool elect1() {
    uint32_t p;
    asm volatile("{ .reg .pred p; elect.sync _|p, 0xFFFFFFFF; selp.b32 %0, 1, 0, p; }" : "=r"(p));
    return p != 0;
}
#define IDESC_F16 ((1u<<4)|(1u<<7)|(1u<<10)|(16u<<17)|(8u<<24))
__device__ __forceinline__ uint64_t mkdesc(uint32_t addr) {
    return ((uint64_t)2 << 61) | ((uint64_t)1 << 46) | ((uint64_t)64 << 32) | ((uint64_t)1 << 16)
         | ((uint64_t)(addr >> 4) & 0x3FFF);
}
#if HAS_TC
__device__ __forceinline__ void mma_ss(uint32_t d, uint64_t ad, uint64_t bd, uint32_t en) {
    asm volatile("{\n\t.reg .pred p;\n\tsetp.ne.u32 p, %4, 0;\n\t"
        "tcgen05.mma.cta_group::1.kind::f16 [%0], %1, %2, %3, {%5,%5,%5,%5}, p;\n\t}"
        :: "r"(d), "l"(ad), "l"(bd), "r"(IDESC_F16), "r"(en), "r"(0u) : "memory");
}
__device__ __forceinline__ void mma_tile3(uint32_t d, uint32_t a_addr, uint32_t b_addr,
                                          uint32_t mbar, bool fresh, bool commit) {
    if (elect1()) {
        uint64_t adb = mkdesc(a_addr), bdb = mkdesc(b_addr);
#pragma unroll
        for (int t = 0; t < 3; t++) {
            uint64_t ao = adb + (t == 2 ? 2048 : 0);
            uint64_t bo = bdb + (t == 1 ? 2048 : 0);
#pragma unroll
            for (int s = 0; s < 8; s++) {
                uint64_t off = (uint64_t)((s >> 2) * 1024 + (s & 3) * 2);
                mma_ss(d, ao + off, bo + off, (t == 0 && s == 0 && fresh) ? 0u : 1u);
            }
        }
        if (commit)
            asm volatile("tcgen05.commit.cta_group::1.mbarrier::arrive::one.shared::cluster.b64 [%0];"
                         :: "r"(mbar) : "memory");
    }
}
#define MBAR_INIT(a, c) asm volatile("mbarrier.init.shared.b64 [%0], %1;" :: "r"(a), "r"(c) : "memory")
#define MBAR_INVAL(a)   asm volatile("mbarrier.inval.shared.b64 [%0];" :: "r"(a) : "memory")
#define MBAR_WAIT(a, par) do { uint32_t _m=(a), _p=(par); \
    asm volatile("{\n\t.reg .pred P1;\n\tWL%=:\n\t" \
        "mbarrier.try_wait.parity.acquire.cta.shared::cta.b64 P1, [%0], %1, 0x989680;\n\t" \
        "@P1 bra.uni WD%=;\n\tbra.uni WL%=;\n\tWD%=:\n\t}" :: "r"(_m), "r"(_p) : "memory"); } while(0)
#define TC_ALLOC(a, n)   asm volatile("tcgen05.alloc.cta_group::1.sync.aligned.shared::cta.b32 [%0], %1;" :: "r"(a), "r"(n) : "memory")
#define TC_DEALLOC(t, n) asm volatile("tcgen05.dealloc.cta_group::1.sync.aligned.b32 %0, %1;" :: "r"(t), "r"(n))
#define TC_FENCE_AFTER()  asm volatile("tcgen05.fence::after_thread_sync;" ::: "memory")
#define TC_FENCE_BEFORE() asm volatile("tcgen05.fence::before_thread_sync;" ::: "memory")
#define FENCE_ASYNC()    asm volatile("fence.proxy.async.shared::cta;" ::: "memory")
#define TC_WAIT_LD()     asm volatile("tcgen05.wait::ld.sync.aligned;" ::: "memory")
#define LDTM32(r, addr) \
    asm volatile("tcgen05.ld.sync.aligned.32x32b.x32.b32 " \
        "{%0,%1,%2,%3,%4,%5,%6,%7,%8,%9,%10,%11,%12,%13,%14,%15," \
        "%16,%17,%18,%19,%20,%21,%22,%23,%24,%25,%26,%27,%28,%29,%30,%31}, [%32];" \
        : "=r"((r)[0]),"=r"((r)[1]),"=r"((r)[2]),"=r"((r)[3]),"=r"((r)[4]),"=r"((r)[5]),"=r"((r)[6]),"=r"((r)[7]), \
          "=r"((r)[8]),"=r"((r)[9]),"=r"((r)[10]),"=r"((r)[11]),"=r"((r)[12]),"=r"((r)[13]),"=r"((r)[14]),"=r"((r)[15]), \
          "=r"((r)[16]),"=r"((r)[17]),"=r"((r)[18]),"=r"((r)[19]),"=r"((r)[20]),"=r"((r)[21]),"=r"((r)[22]),"=r"((r)[23]), \
          "=r"((r)[24]),"=r"((r)[25]),"=r"((r)[26]),"=r"((r)[27]),"=r"((r)[28]),"=r"((r)[29]),"=r"((r)[30]),"=r"((r)[31]) \
        : "r"(addr))
#endif

// smem layout: S1 64KB | S2 64KB | stage 67584 (also 3rd pair buffer) | aux
#define STAGE_OFF 131072
#define AUX_OFF   (131072 + 128 * TS * 4)
#define SMEMSZ    (AUX_OFF + 2112)

// ================= k_prep: 5 weight transposes -> pair tiles =================
__global__ void __launch_bounds__(256) k_prep(const float* __restrict__ Wq, const float* __restrict__ Wk,
        const float* __restrict__ Wv, const float* __restrict__ Wg, const float* __restrict__ Wo) {
    const float* W = blockIdx.x == 0 ? Wq : blockIdx.x == 1 ? Wk : blockIdx.x == 2 ? Wv
                   : blockIdx.x == 3 ? Wg : Wo;
    fill_t<256>(g_WT + blockIdx.x * 16384, W, 128);
}

// ================= k_proj: grid 256 = ci*4 + p =================
__global__ void __launch_bounds__(512) k_proj(const float* __restrict__ tokens,
        const float* __restrict__ g1, const float* __restrict__ b1) {
#if HAS_TC
    extern __shared__ __align__(1024) char smem[];
    uint32_t* S1 = (uint32_t*)smem;
    uint32_t* S2 = (uint32_t*)(smem + 65536);
    float* stage = (float*)(smem + STAGE_OFF);
    char* aux = smem + AUX_OFF;
    uint32_t auxa = smem_u32(aux), mbar = auxa + 8;
    int tid = threadIdx.x, wid = tid >> 5;
    int p = blockIdx.x & 3, ci = blockIdx.x >> 2;

    if (wid == 0) TC_ALLOC(auxa, 256);
    if (tid == 0) MBAR_INIT(mbar, 1);
    __syncthreads();
    uint32_t tmem;
    asm volatile("ld.shared.b32 %0,[%1];" : "=r"(tmem) : "r"(auxa));
    uint32_t uS1 = smem_u32(S1), uS2 = smem_u32(S2);

    ln512(tokens + (size_t)ci * 16384, stage, g1, b1);
    __syncthreads();
    fill_nt<512>(S1, stage, TS);
    cp64k<512>(S2, g_WT + p * 16384);
    FENCE_ASYNC();
    __syncthreads();
    if (wid == 0) mma_tile3(tmem, uS1, uS2, mbar, true, true);
    MBAR_WAIT(mbar, 0); TC_FENCE_AFTER();

    if (tid < 256) {
        int t = tid & 127, wg = tid >> 7;
        uint32_t rr[2][32];
        LDTM32(rr[0], tmem + (wg * 2 + 0) * 32); TC_WAIT_LD();
        LDTM32(rr[1], tmem + (wg * 2 + 1) * 32); TC_WAIT_LD();
        if (p == 0) {   // Qp pair direct
            uint32_t* dst = g_QpP + (size_t)ci * 16384;
#pragma unroll
            for (int b = 0; b < 2; b++)
#pragma unroll
                for (int j = 0; j < 32; j += 2) {
                    int c = wg * 64 + b * 32 + j;
                    float f0 = phi_f(__uint_as_float(rr[b][j]));
                    float f1 = phi_f(__uint_as_float(rr[b][j + 1]));
                    uint32_t hi, lo; pair2(f0, f1, hi, lo);
                    uint32_t w = bfoff(t, c) >> 2;
                    dst[w] = hi; dst[8192 + w] = lo;
                }
        } else {
#pragma unroll
            for (int b = 0; b < 2; b++)
#pragma unroll
                for (int j = 0; j < 32; j++) {
                    int c = wg * 64 + b * 32 + j;
                    float f = __uint_as_float(rr[b][j]);
                    if (p == 1) f = phi_f(f);
                    stage[t * TS + c] = f;
                }
        }
    }
    __syncthreads();
    if (p == 1) {
        fill_nt<512>(g_KpP + (size_t)ci * 16384, stage, TS);
        fill_t<512>(g_KpTP + (size_t)ci * 16384, stage, TS);
        if (tid < 128) {
            float s = 0.f;
#pragma unroll 4
            for (int t = 0; t < 128; t++) s += stage[t * TS + tid];
            g_uv[ci * Dm + tid] = s;
        }
    } else if (p == 2) {
        stage_out<512>(g_V + (size_t)ci * 16384, stage);
    } else if (p == 3) {
        stage_out<512>(g_G + (size_t)ci * 16384, stage);
    }
    __syncthreads();
    if (tid == 0) MBAR_INVAL(mbar);
    __syncthreads();
    if (wid == 0) TC_DEALLOC(tmem, 256);
#endif
}

// ================= k_gateU: Vg gate + U = Kp^T Vg =================
__global__ void __launch_bounds__(512) k_gateU(const float* __restrict__ bg) {
#if HAS_TC
    extern __shared__ __align__(1024) char smem[];
    uint32_t* S1 = (uint32_t*)smem;
    uint32_t* S2 = (uint32_t*)(smem + 65536);
    float* stage = (float*)(smem + STAGE_OFF);
    char* aux = smem + AUX_OFF;
    uint32_t auxa = smem_u32(aux), mbar = auxa + 8;
    float* bgs = (float*)(aux + 16);
    int tid = threadIdx.x, wid = tid >> 5, ci = blockIdx.x;

    if (wid == 0) TC_ALLOC(auxa, 256);
    if (tid == 0) MBAR_INIT(mbar, 1);
    if (tid < 128) bgs[tid] = bg[tid];
    __syncthreads();
    uint32_t tmem;
    asm volatile("ld.shared.b32 %0,[%1];" : "=r"(tmem) : "r"(auxa));
    uint32_t uS1 = smem_u32(S1), uS2 = smem_u32(S2);

    // gate: Vg = V * sigmoid(G + bg) -> stage
#pragma unroll
    for (int it = 0; it < 8; it++) {
        int i4 = tid + it * 512;
        float4 v = ((const float4*)g_V)[(size_t)ci * 4096 + i4];
        float4 g = ((const float4*)g_G)[(size_t)ci * 4096 + i4];
        int r = i4 >> 5, c = (i4 & 31) * 4;
        float4 o;
        o.x = v.x * sig_f(g.x + bgs[c]);
        o.y = v.y * sig_f(g.y + bgs[c + 1]);
        o.z = v.z * sig_f(g.z + bgs[c + 2]);
        o.w = v.w * sig_f(g.w + bgs[c + 3]);
        *(float4*)&stage[r * TS + c] = o;
    }
    __syncthreads();
    fill_t<512>(S2, stage, TS);                       // VgT pair
    cp64k<512>(S1, g_KpTP + (size_t)ci * 16384);
    cp64k<512>(g_VgTP + (size_t)ci * 16384, S2);      // persist VgT
    FENCE_ASYNC();
    __syncthreads();
    if (wid == 0) mma_tile3(tmem, uS1, uS2, mbar, true, true);   // U
    MBAR_WAIT(mbar, 0); TC_FENCE_AFTER();
    if (tid < 256) {
        int t = tid & 127, wg = tid >> 7;
        uint32_t rr[2][32];
        LDTM32(rr[0], tmem + (wg * 2 + 0) * 32); TC_WAIT_LD();
        LDTM32(rr[1], tmem + (wg * 2 + 1) * 32); TC_WAIT_LD();
#pragma unroll
        for (int b = 0; b < 2; b++)
#pragma unroll
            for (int j = 0; j < 32; j++)
                stage[t * TS + wg * 64 + b * 32 + j] = __uint_as_float(rr[b][j]);
    }
    __syncthreads();
    stage_out<512>(g_U + (size_t)ci * 16384, stage);
    __syncthreads();
    if (tid == 0) MBAR_INVAL(mbar);
    __syncthreads();
    if (wid == 0) TC_DEALLOC(tmem, 256);
#endif
}

// ================= k_prefix: chunk scan -> S^T pair + sv =================
__global__ void __launch_bounds__(256) k_prefix() {
    int bid = blockIdx.x, tid = threadIdx.x;
    if (bid < 64) {
        int b = bid >> 5;
        int e = (bid & 31) * 256 + tid;     // 0..8191
        int m = e & 127, k = (e >> 7) * 2;  // row m, k-pair (k, k+1)
        float u0[CPB], u1[CPB];
#pragma unroll
        for (int c = 0; c < CPB; c++) {
            const float* U = g_U + (size_t)(b * CPB + c) * 16384;
            u0[c] = U[k * 128 + m];
            u1[c] = U[(k + 1) * 128 + m];
        }
        uint32_t w = bfoff(m, k) >> 2;
        float a0 = 0.f, a1 = 0.f;
#pragma unroll
        for (int c = 0; c < CPB; c++) {
            uint32_t hi, lo; pair2(a0, a1, hi, lo);
            uint32_t* dst = g_STP + (size_t)(b * CPB + c) * 16384;
            dst[w] = hi; dst[8192 + w] = lo;
            a0 += u0[c]; a1 += u1[c];
        }
    } else {                                 // sv scan
        int b = tid >> 7, h = tid & 127;
        float u[CPB];
#pragma unroll
        for (int c = 0; c < CPB; c++) u[c] = g_uv[(b * CPB + c) * Dm + h];
        float a = 0.f;
#pragma unroll
        for (int c = 0; c < CPB; c++) {
            g_sv[(b * CPB + c) * Dm + h] = a;
            a += u[c];
        }
    }
}

// ================= k_attn1: inter + scores + mask/denom + intra -> At pair =================
__global__ void __launch_bounds__(512) k_attn1() {
#if HAS_TC
    extern __shared__ __align__(1024) char smem[];
    uint32_t* S1 = (uint32_t*)smem;
    uint32_t* S2 = (uint32_t*)(smem + 65536);
    uint32_t* S3 = (uint32_t*)(smem + STAGE_OFF);   // stage region as 3rd pair buffer
    char* aux = smem + AUX_OFF;
    uint32_t auxa = smem_u32(aux), mbar = auxa + 8;
    float* svs  = (float*)(aux + 16);
    float* denq = svs + 128;
    float* denp = denq + 128;    // [256]
    int tid = threadIdx.x, wid = tid >> 5, ci = blockIdx.x;

    if (wid == 0) TC_ALLOC(auxa, 256);
    if (tid == 0) MBAR_INIT(mbar, 1);
    if (tid < 128) svs[tid] = g_sv[ci * Dm + tid];
    __syncthreads();
    uint32_t tmem;
    asm volatile("ld.shared.b32 %0,[%1];" : "=r"(tmem) : "r"(auxa));
    uint32_t D0 = tmem, D1 = tmem + 128;
    uint32_t uS1 = smem_u32(S1), uS2 = smem_u32(S2), uS3 = smem_u32(S3);

    cp64k<512>(S1, g_QpP + (size_t)ci * 16384);
    cp64k<512>(S2, g_KpP + (size_t)ci * 16384);
    cp64k<512>(S3, g_STP + (size_t)ci * 16384);
    FENCE_ASYNC();
    __syncthreads();
    if (wid == 0) {
        mma_tile3(D0, uS1, uS3, mbar, true, false);   // inter = Qp @ S
        mma_tile3(D1, uS1, uS2, mbar, true, true);    // scores = Qp @ Kp^T
    }
    MBAR_WAIT(mbar, 0); TC_FENCE_AFTER();
    cp64k<512>(S3, g_VgTP + (size_t)ci * 16384);      // Vg^T (S3 free after inter)
    __syncthreads();
    // phase A: den_inter[t] = Qp[t,:] . sv   (from S1 pair)
    if (tid < 128) {
        float den = 0.f;
#pragma unroll 4
        for (int cp = 0; cp < 64; cp++) {
            uint32_t w = bfoff(tid, 2 * cp) >> 2;
            float2 h = unpackbf2(S1[w]);
            float2 l = unpackbf2(S1[8192 + w]);
            den += (h.x + l.x) * svs[2 * cp] + (h.y + l.y) * svs[2 * cp + 1];
        }
        denq[tid] = den;
    }
    __syncthreads();
    // phase B: mask + partial denom; Amask pair -> S1
    if (tid < 256) {
        int t = tid & 127, wg = tid >> 7;
        float den = 0.f;
        uint32_t rr[32];
#pragma unroll
        for (int b = 0; b < 2; b++) {
            LDTM32(rr, D1 + (wg * 2 + b) * 32); TC_WAIT_LD();
#pragma unroll
            for (int j = 0; j < 32; j += 2) {
                int c = wg * 64 + b * 32 + j;
                float f0 = __uint_as_float(rr[j]);     if (c > t)     f0 = 0.f;
                float f1 = __uint_as_float(rr[j + 1]); if (c + 1 > t) f1 = 0.f;
                den += f0 + f1;
                uint32_t hi, lo; pair2(f0, f1, hi, lo);
                uint32_t w = bfoff(t, c) >> 2;
                S1[w] = hi; S1[8192 + w] = lo;
            }
        }
        denp[wg * 128 + t] = den;
    }
    FENCE_ASYNC(); TC_FENCE_BEFORE();
    __syncthreads();
    if (wid == 0) mma_tile3(D0, uS1, uS3, mbar, false, true);   // D0 += Amask @ Vg
    MBAR_WAIT(mbar, 1); TC_FENCE_AFTER();
    // divide epilogue -> At pair direct to gmem
    if (tid < 256) {
        int t = tid & 127, wg = tid >> 7;
        float inv = 1.f / fmaxf(denq[t] + denp[t] + denp[128 + t], ATT_EPS);
        uint32_t* dst = g_AtP + (size_t)ci * 16384;
        uint32_t rr[32];
#pragma unroll
        for (int b = 0; b < 2; b++) {
            LDTM32(rr, D0 + (wg * 2 + b) * 32); TC_WAIT_LD();
#pragma unroll
            for (int j = 0; j < 32; j += 2) {
                int c = wg * 64 + b * 32 + j;
                float f0 = __uint_as_float(rr[j]) * inv;
                float f1 = __uint_as_float(rr[j + 1]) * inv;
                uint32_t hi, lo; pair2(f0, f1, hi, lo);
                uint32_t w = bfoff(t, c) >> 2;
                dst[w] = hi; dst[8192 + w] = lo;
            }
        }
    }
    __syncthreads();
    if (tid == 0) MBAR_INVAL(mbar);
    __syncthreads();
    if (wid == 0) TC_DEALLOC(tmem, 256);
#endif
}

// ================= k_attn2: out = LN2(tokens + 0.1 * At @ Wo) =================
__global__ void __launch_bounds__(512) k_attn2(const float* __restrict__ tokens,
        const float* __restrict__ g2, const float* __restrict__ b2, float* __restrict__ out) {
#if HAS_TC
    extern __shared__ __align__(1024) char smem[];
    uint32_t* S1 = (uint32_t*)smem;
    uint32_t* S2 = (uint32_t*)(smem + 65536);
    float* stage = (float*)(smem + STAGE_OFF);
    char* aux = smem + AUX_OFF;
    uint32_t auxa = smem_u32(aux), mbar = auxa + 8;
    int tid = threadIdx.x, wid = tid >> 5, ci = blockIdx.x;

    if (wid == 0) TC_ALLOC(auxa, 256);
    if (tid == 0) MBAR_INIT(mbar, 1);
    __syncthreads();
    uint32_t tmem;
    asm volatile("ld.shared.b32 %0,[%1];" : "=r"(tmem) : "r"(auxa));
    uint32_t uS1 = smem_u32(S1), uS2 = smem_u32(S2);

    cp64k<512>(S1, g_AtP + (size_t)ci * 16384);
    cp64k<512>(S2, g_WT + 4 * 16384);
    // tokens tile -> stage (coalesced), for residual
    {
        const float4* t4 = (const float4*)(tokens + (size_t)ci * 16384);
#pragma unroll
        for (int it = 0; it < 8; it++) {
            int p = tid + it * 512;
            int r = p >> 5, c = (p & 31) * 4;
            *(float4*)&stage[r * TS + c] = t4[p];
        }
    }
    FENCE_ASYNC();
    __syncthreads();
    if (wid == 0) mma_tile3(tmem, uS1, uS2, mbar, true, true);
    MBAR_WAIT(mbar, 0); TC_FENCE_AFTER();
    if (tid < 256) {
        int t = tid & 127, wg = tid >> 7;
        uint32_t rr[2][32];
        LDTM32(rr[0], tmem + (wg * 2 + 0) * 32); TC_WAIT_LD();
        LDTM32(rr[1], tmem + (wg * 2 + 1) * 32); TC_WAIT_LD();
#pragma unroll
        for (int b = 0; b < 2; b++)
#pragma unroll
            for (int j = 0; j < 32; j++) {
                int c = wg * 64 + b * 32 + j;
                stage[t * TS + c] += 0.1f * __uint_as_float(rr[b][j]);
            }
    }
    __syncthreads();
    // LN2: warp per row, coalesced out
    {
        int lane = tid & 31;
        float4 gg = ((const float4*)g2)[lane], bb = ((const float4*)b2)[lane];
        for (int r = wid; r < 128; r += 16) {
            float4 v = *(const float4*)&stage[r * TS + lane * 4];
            float s = v.x + v.y + v.z + v.w;
            float ss = v.x * v.x + v.y * v.y + v.z * v.z + v.w * v.w;
#pragma unroll
            for (int o = 16; o; o >>= 1) {
                s  += __shfl_xor_sync(0xffffffffu, s,  o);
                ss += __shfl_xor_sync(0xffffffffu, ss, o);
            }
            float mu = s * (1.f / 128.f);
            float inv = rsqrtf(ss * (1.f / 128.f) - mu * mu + LN_EPS);
            float4 o4;
            o4.x = (v.x - mu) * inv * gg.x + bb.x;
            o4.y = (v.y - mu) * inv * gg.y + bb.y;
            o4.z = (v.z - mu) * inv * gg.z + bb.z;
            o4.w = (v.w - mu) * inv * gg.w + bb.w;
            *(float4*)&out[((size_t)ci * 128 + r) * 128 + lane * 4] = o4;
        }
    }
    __syncthreads();
    if (tid == 0) MBAR_INVAL(mbar);
    __syncthreads();
    if (wid == 0) TC_DEALLOC(tmem, 256);
#endif
}

extern "C" void kernel_launch(void* const* d_in, const int* in_sizes, int n_in,
                              void* d_out, int out_size) {
    const float* tokens = (const float*)d_in[0];
    const float* Wq = (const float*)d_in[1];
    const float* Wk = (const float*)d_in[2];
    const float* Wv = (const float*)d_in[3];
    const float* Wg = (const float*)d_in[4];
    const float* bg = (const float*)d_in[5];
    const float* Wo = (const float*)d_in[6];
    const float* g1 = (const float*)d_in[7];
    const float* b1 = (const float*)d_in[8];
    const float* g2 = (const float*)d_in[9];
    const float* b2 = (const float*)d_in[10];
    float* out = (float*)d_out;

    cudaFuncSetAttribute(k_proj,  cudaFuncAttributeMaxDynamicSharedMemorySize, SMEMSZ);
    cudaFuncSetAttribute(k_gateU, cudaFuncAttributeMaxDynamicSharedMemorySize, SMEMSZ);
    cudaFuncSetAttribute(k_attn1, cudaFuncAttributeMaxDynamicSharedMemorySize, SMEMSZ);
    cudaFuncSetAttribute(k_attn2, cudaFuncAttributeMaxDynamicSharedMemorySize, SMEMSZ);

    k_prep<<<5, 256>>>(Wq, Wk, Wv, Wg, Wo);
    k_proj<<<256, 512, SMEMSZ>>>(tokens, g1, b1);
    k_gateU<<<64, 512, SMEMSZ>>>(bg);
    k_prefix<<<65, 256>>>();
    k_attn1<<<64, 512, SMEMSZ>>>();
    k_attn2<<<64, 512, SMEMSZ>>>(tokens, g2, b2, out);
}

// round 8
// speedup vs baseline: 2.8166x; 1.5825x over previous
#include <cuda_runtime.h>
#include <cuda_bf16.h>
#include <math.h>
#include <stdint.h>

#define Dm 128
#define TS 132
#define NCH 64
#define CPB 32
#define LN_EPS 1e-5f
#define ATT_EPS 1e-6f

#if defined(__CUDA_ARCH_FEAT_SM103_ALL) || defined(__CUDA_ARCH_FEAT_SM100_ALL)
#define HAS_TC 1
#else
#define HAS_TC 0
#endif

// pair tiles: u32[16384] = hi plane [0..8191], lo plane [8192..16383]
__device__ uint32_t g_QpP [NCH * 16384];
__device__ uint32_t g_KpP [NCH * 16384];
__device__ uint32_t g_KpTP[NCH * 16384];
__device__ uint32_t g_VgTP[NCH * 16384];
__device__ float g_V [NCH * 16384];
__device__ float g_G [NCH * 16384];
__device__ float g_U [NCH * 16384];
__device__ float g_S [NCH * 16384];
__device__ float g_uv[NCH * Dm];
__device__ float g_sv[NCH * Dm];

// ================= helpers =================
static __device__ __forceinline__ uint32_t smem_u32(const void* p) {
    uint32_t a;
    asm("{ .reg .u64 t; cvta.to.shared.u64 t, %1; cvt.u32.u64 %0, t; }" : "=r"(a) : "l"(p));
    return a;
}
__device__ __forceinline__ float phi_f(float x) { return x > 0.f ? x + 1.f : __expf(x); }
__device__ __forceinline__ float sig_f(float x) { return 1.f / (1.f + __expf(-x)); }

__device__ __forceinline__ uint32_t bfoff(int row, int col) {
    uint32_t u = (uint32_t)(((row >> 3) + (col >> 6) * 16) * 1024 + (row & 7) * 128 + (col & 63) * 2);
    return u ^ ((u >> 3) & 0x70);
}
__device__ __forceinline__ uint32_t packbf(float a, float b) {
    __nv_bfloat16 ha = __float2bfloat16(a), hb = __float2bfloat16(b);
    return (uint32_t)__bfloat16_as_ushort(ha) | ((uint32_t)__bfloat16_as_ushort(hb) << 16);
}
__device__ __forceinline__ void pair2(float a, float b, uint32_t& hi, uint32_t& lo) {
    float ra = __bfloat162float(__float2bfloat16(a));
    float rb = __bfloat162float(__float2bfloat16(b));
    hi = packbf(a, b);
    lo = packbf(a - ra, b - rb);
}
__device__ __forceinline__ float2 unpackbf2(uint32_t u) {
    __nv_bfloat162 v = *reinterpret_cast<__nv_bfloat162*>(&u);
    return __bfloat1622float2(v);
}

// non-transposed pair fill: dst(row=r, k=c) = src[r][c]   (gmem-coalesced dst)
template<int NT>
__device__ __forceinline__ void fill_nt(uint32_t* __restrict__ dst, const float* __restrict__ src, int ld) {
    int tid = threadIdx.x;
#pragma unroll
    for (int it = 0; it < 8192 / NT; it++) {
        int p = tid + it * NT;
        int r = p >> 6, c = (p & 63) * 2;
        float2 v = *(const float2*)&src[r * ld + c];
        uint32_t hi, lo; pair2(v.x, v.y, hi, lo);
        uint32_t w = bfoff(r, c) >> 2;
        dst[w] = hi; dst[8192 + w] = lo;
    }
}
// transposed pair fill: dst(row=n, k=k) = src[k][n]   (dst should be SMEM: scattered rows)
template<int NT>
__device__ __forceinline__ void fill_t(uint32_t* __restrict__ dst, const float* __restrict__ src, int ld) {
    int tid = threadIdx.x;
#pragma unroll
    for (int it = 0; it < 8192 / NT; it++) {
        int p = tid + it * NT;
        int n = p & 127, k = (p >> 7) * 2;
        float f0 = src[k * ld + n];
        float f1 = src[(k + 1) * ld + n];
        uint32_t hi, lo; pair2(f0, f1, hi, lo);
        uint32_t w = bfoff(n, k) >> 2;
        dst[w] = hi; dst[8192 + w] = lo;
    }
}
template<int NT>
__device__ __forceinline__ void cp64k(void* __restrict__ dst, const void* __restrict__ src) {
    float4* d = (float4*)dst; const float4* s = (const float4*)src;
    int tid = threadIdx.x;
#pragma unroll
    for (int it = 0; it < 4096 / NT; it++) d[tid + it * NT] = s[tid + it * NT];
}
template<int NT>
__device__ __forceinline__ void stage_out(float* __restrict__ g, const float* __restrict__ stage) {
    int tid = threadIdx.x;
#pragma unroll
    for (int it = 0; it < 4096 / NT; it++) {
        int p = tid + it * NT;
        int r = p >> 5, c = (p & 31) * 4;
        *(float4*)&g[r * 128 + c] = *(const float4*)&stage[r * TS + c];
    }
}
__device__ __forceinline__ void ln512(const float* __restrict__ tok, float* __restrict__ buf,
                                      const float* __restrict__ g1, const float* __restrict__ b1) {
    int lane = threadIdx.x & 31, wid = threadIdx.x >> 5;
    float4 gg = ((const float4*)g1)[lane], bb = ((const float4*)b1)[lane];
    for (int r = wid; r < 128; r += 16) {
        float4 v = ((const float4*)(tok + r * 128))[lane];
        float s = v.x + v.y + v.z + v.w;
        float ss = v.x * v.x + v.y * v.y + v.z * v.z + v.w * v.w;
#pragma unroll
        for (int o = 16; o; o >>= 1) {
            s  += __shfl_xor_sync(0xffffffffu, s,  o);
            ss += __shfl_xor_sync(0xffffffffu, ss, o);
        }
        float mu = s * (1.f / 128.f);
        float inv = rsqrtf(ss * (1.f / 128.f) - mu * mu + LN_EPS);
        float* d = &buf[r * TS + lane * 4];
        d[0] = (v.x - mu) * inv * gg.x + bb.x;
        d[1] = (v.y - mu) * inv * gg.y + bb.y;
        d[2] = (v.z - mu) * inv * gg.z + bb.z;
        d[3] = (v.w - mu) * inv * gg.w + bb.w;
    }
}

// ================= tcgen05 plumbing =================
static __device__ __forceinline__ bool elect1() {
    uint32_t p;
    asm volatile("{ .reg .pred p; elect.sync _|p, 0xFFFFFFFF; selp.b32 %0, 1, 0, p; }" : "=r"(p));
    return p != 0;
}
#define IDESC_F16 ((1u<<4)|(1u<<7)|(1u<<10)|(16u<<17)|(8u<<24))
__device__ __forceinline__ uint64_t mkdesc(uint32_t addr) {
    return ((uint64_t)2 << 61) | ((uint64_t)1 << 46) | ((uint64_t)64 << 32) | ((uint64_t)1 << 16)
         | ((uint64_t)(addr >> 4) & 0x3FFF);
}
#if HAS_TC
__device__ __forceinline__ void mma_ss(uint32_t d, uint64_t ad, uint64_t bd, uint32_t en) {
    asm volatile("{\n\t.reg .pred p;\n\tsetp.ne.u32 p, %4, 0;\n\t"
        "tcgen05.mma.cta_group::1.kind::f16 [%0], %1, %2, %3, {%5,%5,%5,%5}, p;\n\t}"
        :: "r"(d), "l"(ad), "l"(bd), "r"(IDESC_F16), "r"(en), "r"(0u) : "memory");
}
__device__ __forceinline__ void mma_tile3(uint32_t d, uint32_t a_addr, uint32_t b_addr,
                                          uint32_t mbar, bool fresh, bool commit) {
    if (elect1()) {
        uint64_t adb = mkdesc(a_addr), bdb = mkdesc(b_addr);
#pragma unroll
        for (int t = 0; t < 3; t++) {
            uint64_t ao = adb + (t == 2 ? 2048 : 0);
            uint64_t bo = bdb + (t == 1 ? 2048 : 0);
#pragma unroll
            for (int s = 0; s < 8; s++) {
                uint64_t off = (uint64_t)((s >> 2) * 1024 + (s & 3) * 2);
                mma_ss(d, ao + off, bo + off, (t == 0 && s == 0 && fresh) ? 0u : 1u);
            }
        }
        if (commit)
            asm volatile("tcgen05.commit.cta_group::1.mbarrier::arrive::one.shared::cluster.b64 [%0];"
                         :: "r"(mbar) : "memory");
    }
}
#define MBAR_INIT(a, c) asm volatile("mbarrier.init.shared.b64 [%0], %1;" :: "r"(a), "r"(c) : "memory")
#define MBAR_INVAL(a)   asm volatile("mbarrier.inval.shared.b64 [%0];" :: "r"(a) : "memory")
#define MBAR_WAIT(a, par) do { uint32_t _m=(a), _p=(par); \
    asm volatile("{\n\t.reg .pred P1;\n\tWL%=:\n\t" \
        "mbarrier.try_wait.parity.acquire.cta.shared::cta.b64 P1, [%0], %1, 0x989680;\n\t" \
        "@P1 bra.uni WD%=;\n\tbra.uni WL%=;\n\tWD%=:\n\t}" :: "r"(_m), "r"(_p) : "memory"); } while(0)
#define TC_ALLOC(a, n)   asm volatile("tcgen05.alloc.cta_group::1.sync.aligned.shared::cta.b32 [%0], %1;" :: "r"(a), "r"(n) : "memory")
#define TC_DEALLOC(t, n) asm volatile("tcgen05.dealloc.cta_group::1.sync.aligned.b32 %0, %1;" :: "r"(t), "r"(n))
#define TC_FENCE_AFTER()  asm volatile("tcgen05.fence::after_thread_sync;" ::: "memory")
#define TC_FENCE_BEFORE() asm volatile("tcgen05.fence::before_thread_sync;" ::: "memory")
#define FENCE_ASYNC()    asm volatile("fence.proxy.async.shared::cta;" ::: "memory")
#define TC_WAIT_LD()     asm volatile("tcgen05.wait::ld.sync.aligned;" ::: "memory")
#define LDTM32(r, addr) \
    asm volatile("tcgen05.ld.sync.aligned.32x32b.x32.b32 " \
        "{%0,%1,%2,%3,%4,%5,%6,%7,%8,%9,%10,%11,%12,%13,%14,%15," \
        "%16,%17,%18,%19,%20,%21,%22,%23,%24,%25,%26,%27,%28,%29,%30,%31}, [%32];" \
        : "=r"((r)[0]),"=r"((r)[1]),"=r"((r)[2]),"=r"((r)[3]),"=r"((r)[4]),"=r"((r)[5]),"=r"((r)[6]),"=r"((r)[7]), \
          "=r"((r)[8]),"=r"((r)[9]),"=r"((r)[10]),"=r"((r)[11]),"=r"((r)[12]),"=r"((r)[13]),"=r"((r)[14]),"=r"((r)[15]), \
          "=r"((r)[16]),"=r"((r)[17]),"=r"((r)[18]),"=r"((r)[19]),"=r"((r)[20]),"=r"((r)[21]),"=r"((r)[22]),"=r"((r)[23]), \
          "=r"((r)[24]),"=r"((r)[25]),"=r"((r)[26]),"=r"((r)[27]),"=r"((r)[28]),"=r"((r)[29]),"=r"((r)[30]),"=r"((r)[31]) \
        : "r"(addr))
#endif

// smem: S1 64KB | S2 64KB | stage 67584 (doubles as S3 pair buffer) | aux
#define STAGE_OFF 131072
#define AUX_OFF   (131072 + 128 * TS * 4)
#define SMEMSZ    (AUX_OFF + 2112)

// ================= k_proj: grid 256 = ci*4 + p =================
__global__ void __launch_bounds__(512) k_proj(const float* __restrict__ tokens,
        const float* __restrict__ Wq, const float* __restrict__ Wk,
        const float* __restrict__ Wv, const float* __restrict__ Wg,
        const float* __restrict__ g1, const float* __restrict__ b1) {
#if HAS_TC
    extern __shared__ __align__(1024) char smem[];
    uint32_t* S1 = (uint32_t*)smem;
    uint32_t* S2 = (uint32_t*)(smem + 65536);
    float* stage = (float*)(smem + STAGE_OFF);
    char* aux = smem + AUX_OFF;
    uint32_t auxa = smem_u32(aux), mbar = auxa + 8;
    int tid = threadIdx.x, wid = tid >> 5;
    int p = blockIdx.x & 3, ci = blockIdx.x >> 2;
    const float* W = p == 0 ? Wq : p == 1 ? Wk : p == 2 ? Wv : Wg;

    if (wid == 0) TC_ALLOC(auxa, 256);
    if (tid == 0) MBAR_INIT(mbar, 1);
    __syncthreads();
    uint32_t tmem;
    asm volatile("ld.shared.b32 %0,[%1];" : "=r"(tmem) : "r"(auxa));
    uint32_t uS1 = smem_u32(S1), uS2 = smem_u32(S2);

    ln512(tokens + (size_t)ci * 16384, stage, g1, b1);
    __syncthreads();
    fill_nt<512>(S1, stage, TS);
    fill_t<512>(S2, W, 128);
    FENCE_ASYNC();
    __syncthreads();
    if (wid == 0) mma_tile3(tmem, uS1, uS2, mbar, true, true);
    MBAR_WAIT(mbar, 0); TC_FENCE_AFTER();

    if (tid < 256) {
        int t = tid & 127, wg = tid >> 7;
        uint32_t rr[2][32];
        LDTM32(rr[0], tmem + (wg * 2 + 0) * 32);
        LDTM32(rr[1], tmem + (wg * 2 + 1) * 32);
        TC_WAIT_LD();
        if (p == 0) {   // Qp pair -> S1 (smem stage), coalesced copy out later
#pragma unroll
            for (int b = 0; b < 2; b++)
#pragma unroll
                for (int j = 0; j < 32; j += 2) {
                    int c = wg * 64 + b * 32 + j;
                    float f0 = phi_f(__uint_as_float(rr[b][j]));
                    float f1 = phi_f(__uint_as_float(rr[b][j + 1]));
                    uint32_t hi, lo; pair2(f0, f1, hi, lo);
                    uint32_t w = bfoff(t, c) >> 2;
                    S1[w] = hi; S1[8192 + w] = lo;
                }
        } else {
#pragma unroll
            for (int b = 0; b < 2; b++)
#pragma unroll
                for (int j = 0; j < 32; j++) {
                    int c = wg * 64 + b * 32 + j;
                    float f = __uint_as_float(rr[b][j]);
                    if (p == 1) f = phi_f(f);
                    stage[t * TS + c] = f;
                }
        }
    }
    __syncthreads();
    if (p == 0) {
        cp64k<512>(g_QpP + (size_t)ci * 16384, S1);
    } else if (p == 1) {
        fill_nt<512>(g_KpP + (size_t)ci * 16384, stage, TS);   // gmem-coalesced
        fill_t<512>(S2, stage, TS);                            // KpT pair -> smem
        if (tid < 128) {
            float s = 0.f;
#pragma unroll 4
            for (int t = 0; t < 128; t++) s += stage[t * TS + tid];
            g_uv[ci * Dm + tid] = s;
        }
        __syncthreads();
        cp64k<512>(g_KpTP + (size_t)ci * 16384, S2);
    } else if (p == 2) {
        stage_out<512>(g_V + (size_t)ci * 16384, stage);
    } else {
        stage_out<512>(g_G + (size_t)ci * 16384, stage);
    }
    __syncthreads();
    if (tid == 0) MBAR_INVAL(mbar);
    __syncthreads();
    if (wid == 0) TC_DEALLOC(tmem, 256);
#endif
}

// ================= k_gateU: gate + U = Kp^T Vg =================
__global__ void __launch_bounds__(512) k_gateU(const float* __restrict__ bg) {
#if HAS_TC
    extern __shared__ __align__(1024) char smem[];
    uint32_t* S1 = (uint32_t*)smem;
    uint32_t* S2 = (uint32_t*)(smem + 65536);
    float* stage = (float*)(smem + STAGE_OFF);
    char* aux = smem + AUX_OFF;
    uint32_t auxa = smem_u32(aux), mbar = auxa + 8;
    float* bgs = (float*)(aux + 16);
    int tid = threadIdx.x, wid = tid >> 5, ci = blockIdx.x;

    if (wid == 0) TC_ALLOC(auxa, 256);
    if (tid == 0) MBAR_INIT(mbar, 1);
    if (tid < 128) bgs[tid] = bg[tid];
    __syncthreads();
    uint32_t tmem;
    asm volatile("ld.shared.b32 %0,[%1];" : "=r"(tmem) : "r"(auxa));
    uint32_t uS1 = smem_u32(S1), uS2 = smem_u32(S2);

#pragma unroll
    for (int it = 0; it < 8; it++) {
        int i4 = tid + it * 512;
        float4 v = ((const float4*)g_V)[(size_t)ci * 4096 + i4];
        float4 g = ((const float4*)g_G)[(size_t)ci * 4096 + i4];
        int r = i4 >> 5, c = (i4 & 31) * 4;
        float4 o;
        o.x = v.x * sig_f(g.x + bgs[c]);
        o.y = v.y * sig_f(g.y + bgs[c + 1]);
        o.z = v.z * sig_f(g.z + bgs[c + 2]);
        o.w = v.w * sig_f(g.w + bgs[c + 3]);
        *(float4*)&stage[r * TS + c] = o;
    }
    __syncthreads();
    fill_t<512>(S2, stage, TS);                    // VgT pair (smem)
    cp64k<512>(S1, g_KpTP + (size_t)ci * 16384);
    cp64k<512>(g_VgTP + (size_t)ci * 16384, S2);   // persist VgT (coalesced)
    FENCE_ASYNC();
    __syncthreads();
    if (wid == 0) mma_tile3(tmem, uS1, uS2, mbar, true, true);   // U
    MBAR_WAIT(mbar, 0); TC_FENCE_AFTER();
    if (tid < 256) {
        int t = tid & 127, wg = tid >> 7;
        uint32_t rr[2][32];
        LDTM32(rr[0], tmem + (wg * 2 + 0) * 32);
        LDTM32(rr[1], tmem + (wg * 2 + 1) * 32);
        TC_WAIT_LD();
#pragma unroll
        for (int b = 0; b < 2; b++)
#pragma unroll
            for (int j = 0; j < 32; j++)
                stage[t * TS + wg * 64 + b * 32 + j] = __uint_as_float(rr[b][j]);
    }
    __syncthreads();
    stage_out<512>(g_U + (size_t)ci * 16384, stage);
    __syncthreads();
    if (tid == 0) MBAR_INVAL(mbar);
    __syncthreads();
    if (wid == 0) TC_DEALLOC(tmem, 256);
#endif
}

// ================= k_prefix: coalesced fp32 scan =================
__global__ void __launch_bounds__(256) k_prefix() {
    int bid = blockIdx.x, tid = threadIdx.x;
    if (bid < 128) {
        int g = bid * 256 + tid;               // 0..32767
        int b = g >> 14, e = g & 16383;
        const float* U = g_U + (size_t)b * CPB * 16384 + e;
        float* S = g_S + (size_t)b * CPB * 16384 + e;
        float acc = 0.f;
#pragma unroll
        for (int c0 = 0; c0 < CPB; c0 += 8) {
            float v[8];
#pragma unroll
            for (int j = 0; j < 8; j++) v[j] = U[(size_t)(c0 + j) * 16384];
#pragma unroll
            for (int j = 0; j < 8; j++) { S[(size_t)(c0 + j) * 16384] = acc; acc += v[j]; }
        }
    } else {
        int b = tid >> 7, h = tid & 127;
        float acc = 0.f;
#pragma unroll
        for (int c0 = 0; c0 < CPB; c0 += 8) {
            float v[8];
#pragma unroll
            for (int j = 0; j < 8; j++) v[j] = g_uv[(b * CPB + c0 + j) * Dm + h];
#pragma unroll
            for (int j = 0; j < 8; j++) { g_sv[(b * CPB + c0 + j) * Dm + h] = acc; acc += v[j]; }
        }
    }
}

// ===== k_attn (fused): inter+scores -> mask/denom -> intra -> /denom -> @Wo -> +res -> LN2 =====
__global__ void __launch_bounds__(512) k_attn(const float* __restrict__ tokens,
        const float* __restrict__ Wo, const float* __restrict__ g2,
        const float* __restrict__ b2, float* __restrict__ out) {
#if HAS_TC
    extern __shared__ __align__(1024) char smem[];
    uint32_t* S1 = (uint32_t*)smem;
    uint32_t* S2 = (uint32_t*)(smem + 65536);
    uint32_t* S3 = (uint32_t*)(smem + STAGE_OFF);
    char* aux = smem + AUX_OFF;
    uint32_t auxa = smem_u32(aux), mbar = auxa + 8;
    float* svs  = (float*)(aux + 16);
    float* denq = svs + 128;
    float* denp = denq + 128;    // [256]
    int tid = threadIdx.x, wid = tid >> 5, ci = blockIdx.x;

    if (wid == 0) TC_ALLOC(auxa, 256);
    if (tid == 0) MBAR_INIT(mbar, 1);
    if (tid < 128) svs[tid] = g_sv[ci * Dm + tid];
    __syncthreads();
    uint32_t tmem;
    asm volatile("ld.shared.b32 %0,[%1];" : "=r"(tmem) : "r"(auxa));
    uint32_t D0 = tmem, D1 = tmem + 128;
    uint32_t uS1 = smem_u32(S1), uS2 = smem_u32(S2), uS3 = smem_u32(S3);

    cp64k<512>(S1, g_QpP + (size_t)ci * 16384);
    cp64k<512>(S2, g_KpP + (size_t)ci * 16384);
    fill_t<512>(S3, g_S + (size_t)ci * 16384, 128);     // S^T pair from fp32
    FENCE_ASYNC();
    __syncthreads();
    if (wid == 0) {
        mma_tile3(D0, uS1, uS3, mbar, true, false);     // inter = Qp @ S
        mma_tile3(D1, uS1, uS2, mbar, true, true);      // scores = Qp @ Kp^T
    }
    MBAR_WAIT(mbar, 0); TC_FENCE_AFTER();
    cp64k<512>(S3, g_VgTP + (size_t)ci * 16384);        // Vg^T pair
    __syncthreads();
    // denq[t] = Qp[t,:] . sv  (read S1 pair before it is overwritten)
    if (tid < 128) {
        float den = 0.f;
#pragma unroll 4
        for (int cp = 0; cp < 64; cp++) {
            uint32_t w = bfoff(tid, 2 * cp) >> 2;
            float2 h = unpackbf2(S1[w]);
            float2 l = unpackbf2(S1[8192 + w]);
            den += (h.x + l.x) * svs[2 * cp] + (h.y + l.y) * svs[2 * cp + 1];
        }
        denq[tid] = den;
    }
    __syncthreads();
    // mask + partial denom; Amask pair -> S1
    if (tid < 256) {
        int t = tid & 127, wg = tid >> 7;
        float den = 0.f;
        uint32_t r0[32], r1[32];
        LDTM32(r0, D1 + (wg * 2 + 0) * 32);
        LDTM32(r1, D1 + (wg * 2 + 1) * 32);
        TC_WAIT_LD();
#pragma unroll
        for (int b = 0; b < 2; b++) {
            uint32_t* rr = b ? r1 : r0;
#pragma unroll
            for (int j = 0; j < 32; j += 2) {
                int c = wg * 64 + b * 32 + j;
                float f0 = __uint_as_float(rr[j]);     if (c > t)     f0 = 0.f;
                float f1 = __uint_as_float(rr[j + 1]); if (c + 1 > t) f1 = 0.f;
                den += f0 + f1;
                uint32_t hi, lo; pair2(f0, f1, hi, lo);
                uint32_t w = bfoff(t, c) >> 2;
                S1[w] = hi; S1[8192 + w] = lo;
            }
        }
        denp[wg * 128 + t] = den;
    }
    FENCE_ASYNC(); TC_FENCE_BEFORE();
    __syncthreads();
    if (wid == 0) mma_tile3(D0, uS1, uS3, mbar, false, true);    // D0 += Amask @ Vg
    MBAR_WAIT(mbar, 1); TC_FENCE_AFTER();
    fill_t<512>(S2, Wo, 128);                                    // Wo^T pair (S2 free)
    __syncthreads();
    // divide epilogue -> At pair into S1 (overwrite Amask)
    if (tid < 256) {
        int t = tid & 127, wg = tid >> 7;
        float inv = 1.f / fmaxf(denq[t] + denp[t] + denp[128 + t], ATT_EPS);
        uint32_t r0[32], r1[32];
        LDTM32(r0, D0 + (wg * 2 + 0) * 32);
        LDTM32(r1, D0 + (wg * 2 + 1) * 32);
        TC_WAIT_LD();
#pragma unroll
        for (int b = 0; b < 2; b++) {
            uint32_t* rr = b ? r1 : r0;
#pragma unroll
            for (int j = 0; j < 32; j += 2) {
                int c = wg * 64 + b * 32 + j;
                float f0 = __uint_as_float(rr[j]) * inv;
                float f1 = __uint_as_float(rr[j + 1]) * inv;
                uint32_t hi, lo; pair2(f0, f1, hi, lo);
                uint32_t w = bfoff(t, c) >> 2;
                S1[w] = hi; S1[8192 + w] = lo;
            }
        }
    }
    FENCE_ASYNC(); TC_FENCE_BEFORE();
    __syncthreads();
    if (wid == 0) mma_tile3(D1, uS1, uS2, mbar, true, true);     // out = At @ Wo
    MBAR_WAIT(mbar, 0); TC_FENCE_AFTER();
    // read result into regs, then reuse S1/S2 area as fp32 token stage
    uint32_t o0[32], o1[32];
    int t = tid & 127, wg = (tid >> 7) & 1;
    if (tid < 256) {
        LDTM32(o0, D1 + (wg * 2 + 0) * 32);
        LDTM32(o1, D1 + (wg * 2 + 1) * 32);
        TC_WAIT_LD();
    }
    __syncthreads();
    float* T = (float*)smem;   // 128 x TS fp32 spans S1+S2 (both free)
    {
        const float4* t4 = (const float4*)(tokens + (size_t)ci * 16384);
#pragma unroll
        for (int it = 0; it < 8; it++) {
            int p = tid + it * 512;
            int r = p >> 5, c = (p & 31) * 4;
            *(float4*)&T[r * TS + c] = t4[p];
        }
    }
    __syncthreads();
    if (tid < 256) {
#pragma unroll
        for (int b = 0; b < 2; b++) {
            uint32_t* rr = b ? o1 : o0;
#pragma unroll
            for (int j = 0; j < 32; j++) {
                int c = wg * 64 + b * 32 + j;
                T[t * TS + c] += 0.1f * __uint_as_float(rr[j]);
            }
        }
    }
    __syncthreads();
    {
        int lane = tid & 31;
        float4 gg = ((const float4*)g2)[lane], bb = ((const float4*)b2)[lane];
        for (int r = wid; r < 128; r += 16) {
            float4 v = *(const float4*)&T[r * TS + lane * 4];
            float s = v.x + v.y + v.z + v.w;
            float ss = v.x * v.x + v.y * v.y + v.z * v.z + v.w * v.w;
#pragma unroll
            for (int o = 16; o; o >>= 1) {
                s  += __shfl_xor_sync(0xffffffffu, s,  o);
                ss += __shfl_xor_sync(0xffffffffu, ss, o);
            }
            float mu = s * (1.f / 128.f);
            float inv = rsqrtf(ss * (1.f / 128.f) - mu * mu + LN_EPS);
            float4 o4;
            o4.x = (v.x - mu) * inv * gg.x + bb.x;
            o4.y = (v.y - mu) * inv * gg.y + bb.y;
            o4.z = (v.z - mu) * inv * gg.z + bb.z;
            o4.w = (v.w - mu) * inv * gg.w + bb.w;
            *(float4*)&out[((size_t)ci * 128 + r) * 128 + lane * 4] = o4;
        }
    }
    __syncthreads();
    if (tid == 0) MBAR_INVAL(mbar);
    __syncthreads();
    if (wid == 0) TC_DEALLOC(tmem, 256);
#endif
}

extern "C" void kernel_launch(void* const* d_in, const int* in_sizes, int n_in,
                              void* d_out, int out_size) {
    const float* tokens = (const float*)d_in[0];
    const float* Wq = (const float*)d_in[1];
    const float* Wk = (const float*)d_in[2];
    const float* Wv = (const float*)d_in[3];
    const float* Wg = (const float*)d_in[4];
    const float* bg = (const float*)d_in[5];
    const float* Wo = (const float*)d_in[6];
    const float* g1 = (const float*)d_in[7];
    const float* b1 = (const float*)d_in[8];
    const float* g2 = (const float*)d_in[9];
    const float* b2 = (const float*)d_in[10];
    float* out = (float*)d_out;

    cudaFuncSetAttribute(k_proj,  cudaFuncAttributeMaxDynamicSharedMemorySize, SMEMSZ);
    cudaFuncSetAttribute(k_gateU, cudaFuncAttributeMaxDynamicSharedMemorySize, SMEMSZ);
    cudaFuncSetAttribute(k_attn,  cudaFuncAttributeMaxDynamicSharedMemorySize, SMEMSZ);

    k_proj<<<256, 512, SMEMSZ>>>(tokens, Wq, Wk, Wv, Wg, g1, b1);
    k_gateU<<<64, 512, SMEMSZ>>>(bg);
    k_prefix<<<129, 256>>>();
    k_attn<<<64, 512, SMEMSZ>>>(tokens, Wo, g2, b2, out);
}

// round 9
// speedup vs baseline: 2.8193x; 1.0010x over previous
#include <cuda_runtime.h>
#include <cuda_bf16.h>
#include <math.h>
#include <stdint.h>

#define Dm 128
#define TS 132
#define NCH 64
#define CPB 32
#define LN_EPS 1e-5f
#define ATT_EPS 1e-6f

#if defined(__CUDA_ARCH_FEAT_SM103_ALL) || defined(__CUDA_ARCH_FEAT_SM100_ALL)
#define HAS_TC 1
#else
#define HAS_TC 0
#endif

// pair tiles: u32[16384] = hi plane [0..8191], lo plane [8192..16383]
__device__ uint32_t g_QpP [NCH * 16384];
__device__ uint32_t g_KpP [NCH * 16384];
__device__ uint32_t g_KpTP[NCH * 16384];
__device__ uint32_t g_VgTP[NCH * 16384];
__device__ uint32_t g_STP [NCH * 16384];
__device__ float g_Ut[NCH * 16384];     // U^T per chunk: [m][h]
__device__ float g_uv[NCH * Dm];
__device__ float g_sv[NCH * Dm];

// ================= helpers =================
static __device__ __forceinline__ uint32_t smem_u32(const void* p) {
    uint32_t a;
    asm("{ .reg .u64 t; cvta.to.shared.u64 t, %1; cvt.u32.u64 %0, t; }" : "=r"(a) : "l"(p));
    return a;
}
__device__ __forceinline__ float phi_f(float x) { return x > 0.f ? x + 1.f : __expf(x); }
__device__ __forceinline__ float sig_f(float x) { return 1.f / (1.f + __expf(-x)); }

__device__ __forceinline__ uint32_t bfoff(int row, int col) {
    uint32_t u = (uint32_t)(((row >> 3) + (col >> 6) * 16) * 1024 + (row & 7) * 128 + (col & 63) * 2);
    return u ^ ((u >> 3) & 0x70);
}
__device__ __forceinline__ uint32_t packbf(float a, float b) {
    __nv_bfloat16 ha = __float2bfloat16(a), hb = __float2bfloat16(b);
    return (uint32_t)__bfloat16_as_ushort(ha) | ((uint32_t)__bfloat16_as_ushort(hb) << 16);
}
__device__ __forceinline__ void pair2(float a, float b, uint32_t& hi, uint32_t& lo) {
    float ra = __bfloat162float(__float2bfloat16(a));
    float rb = __bfloat162float(__float2bfloat16(b));
    hi = packbf(a, b);
    lo = packbf(a - ra, b - rb);
}
__device__ __forceinline__ float2 unpackbf2(uint32_t u) {
    __nv_bfloat162 v = *reinterpret_cast<__nv_bfloat162*>(&u);
    return __bfloat1622float2(v);
}

// non-transposed pair fill (dst coalesced-safe): dst(row=r, k=c) = src[r][c]
template<int NT>
__device__ __forceinline__ void fill_nt(uint32_t* __restrict__ dst, const float* __restrict__ src, int ld) {
    int tid = threadIdx.x;
#pragma unroll
    for (int it = 0; it < 8192 / NT; it++) {
        int p = tid + it * NT;
        int r = p >> 6, c = (p & 63) * 2;
        float2 v = *(const float2*)&src[r * ld + c];
        uint32_t hi, lo; pair2(v.x, v.y, hi, lo);
        uint32_t w = bfoff(r, c) >> 2;
        dst[w] = hi; dst[8192 + w] = lo;
    }
}
// transposed pair fill (dst must be SMEM): dst(row=n, k=k) = src[k][n]
template<int NT>
__device__ __forceinline__ void fill_t(uint32_t* __restrict__ dst, const float* __restrict__ src, int ld) {
    int tid = threadIdx.x;
#pragma unroll
    for (int it = 0; it < 8192 / NT; it++) {
        int p = tid + it * NT;
        int n = p & 127, k = (p >> 7) * 2;
        float f0 = src[k * ld + n];
        float f1 = src[(k + 1) * ld + n];
        uint32_t hi, lo; pair2(f0, f1, hi, lo);
        uint32_t w = bfoff(n, k) >> 2;
        dst[w] = hi; dst[8192 + w] = lo;
    }
}
template<int NT>
__device__ __forceinline__ void cp64k(void* __restrict__ dst, const void* __restrict__ src) {
    float4* d = (float4*)dst; const float4* s = (const float4*)src;
    int tid = threadIdx.x;
#pragma unroll
    for (int it = 0; it < 4096 / NT; it++) d[tid + it * NT] = s[tid + it * NT];
}
template<int NT>
__device__ __forceinline__ void stage_out(float* __restrict__ g, const float* __restrict__ stage) {
    int tid = threadIdx.x;
#pragma unroll
    for (int it = 0; it < 4096 / NT; it++) {
        int p = tid + it * NT;
        int r = p >> 5, c = (p & 31) * 4;
        *(float4*)&g[r * 128 + c] = *(const float4*)&stage[r * TS + c];
    }
}
__device__ __forceinline__ void ln512(const float* __restrict__ tok, float* __restrict__ buf,
                                      const float* __restrict__ g1, const float* __restrict__ b1) {
    int lane = threadIdx.x & 31, wid = threadIdx.x >> 5;
    float4 gg = ((const float4*)g1)[lane], bb = ((const float4*)b1)[lane];
    for (int r = wid; r < 128; r += 16) {
        float4 v = ((const float4*)(tok + r * 128))[lane];
        float s = v.x + v.y + v.z + v.w;
        float ss = v.x * v.x + v.y * v.y + v.z * v.z + v.w * v.w;
#pragma unroll
        for (int o = 16; o; o >>= 1) {
            s  += __shfl_xor_sync(0xffffffffu, s,  o);
            ss += __shfl_xor_sync(0xffffffffu, ss, o);
        }
        float mu = s * (1.f / 128.f);
        float inv = rsqrtf(ss * (1.f / 128.f) - mu * mu + LN_EPS);
        float* d = &buf[r * TS + lane * 4];
        d[0] = (v.x - mu) * inv * gg.x + bb.x;
        d[1] = (v.y - mu) * inv * gg.y + bb.y;
        d[2] = (v.z - mu) * inv * gg.z + bb.z;
        d[3] = (v.w - mu) * inv * gg.w + bb.w;
    }
}

// ================= tcgen05 plumbing =================
static __device__ __forceinline__ bool elect1() {
    uint32_t p;
    asm volatile("{ .reg .pred p; elect.sync _|p, 0xFFFFFFFF; selp.b32 %0, 1, 0, p; }" : "=r"(p));
    return p != 0;
}
#define IDESC_F16 ((1u<<4)|(1u<<7)|(1u<<10)|(16u<<17)|(8u<<24))
__device__ __forceinline__ uint64_t mkdesc(uint32_t addr) {
    return ((uint64_t)2 << 61) | ((uint64_t)1 << 46) | ((uint64_t)64 << 32) | ((uint64_t)1 << 16)
         | ((uint64_t)(addr >> 4) & 0x3FFF);
}
#if HAS_TC
__device__ __forceinline__ void mma_ss(uint32_t d, uint64_t ad, uint64_t bd, uint32_t en) {
    asm volatile("{\n\t.reg .pred p;\n\tsetp.ne.u32 p, %4, 0;\n\t"
        "tcgen05.mma.cta_group::1.kind::f16 [%0], %1, %2, %3, {%5,%5,%5,%5}, p;\n\t}"
        :: "r"(d), "l"(ad), "l"(bd), "r"(IDESC_F16), "r"(en), "r"(0u) : "memory");
}
__device__ __forceinline__ void mma_tile3(uint32_t d, uint32_t a_addr, uint32_t b_addr,
                                          uint32_t mbar, bool fresh, bool commit) {
    if (elect1()) {
        uint64_t adb = mkdesc(a_addr), bdb = mkdesc(b_addr);
#pragma unroll
        for (int t = 0; t < 3; t++) {
            uint64_t ao = adb + (t == 2 ? 2048 : 0);
            uint64_t bo = bdb + (t == 1 ? 2048 : 0);
#pragma unroll
            for (int s = 0; s < 8; s++) {
                uint64_t off = (uint64_t)((s >> 2) * 1024 + (s & 3) * 2);
                mma_ss(d, ao + off, bo + off, (t == 0 && s == 0 && fresh) ? 0u : 1u);
            }
        }
        if (commit)
            asm volatile("tcgen05.commit.cta_group::1.mbarrier::arrive::one.shared::cluster.b64 [%0];"
                         :: "r"(mbar) : "memory");
    }
}
#define MBAR_INIT(a, c) asm volatile("mbarrier.init.shared.b64 [%0], %1;" :: "r"(a), "r"(c) : "memory")
#define MBAR_INVAL(a)   asm volatile("mbarrier.inval.shared.b64 [%0];" :: "r"(a) : "memory")
#define MBAR_WAIT(a, par) do { uint32_t _m=(a), _p=(par); \
    asm volatile("{\n\t.reg .pred P1;\n\tWL%=:\n\t" \
        "mbarrier.try_wait.parity.acquire.cta.shared::cta.b64 P1, [%0], %1, 0x989680;\n\t" \
        "@P1 bra.uni WD%=;\n\tbra.uni WL%=;\n\tWD%=:\n\t}" :: "r"(_m), "r"(_p) : "memory"); } while(0)
#define TC_ALLOC(a, n)   asm volatile("tcgen05.alloc.cta_group::1.sync.aligned.shared::cta.b32 [%0], %1;" :: "r"(a), "r"(n) : "memory")
#define TC_DEALLOC(t, n) asm volatile("tcgen05.dealloc.cta_group::1.sync.aligned.b32 %0, %1;" :: "r"(t), "r"(n))
#define TC_FENCE_AFTER()  asm volatile("tcgen05.fence::after_thread_sync;" ::: "memory")
#define TC_FENCE_BEFORE() asm volatile("tcgen05.fence::before_thread_sync;" ::: "memory")
#define FENCE_ASYNC()    asm volatile("fence.proxy.async.shared::cta;" ::: "memory")
#define TC_WAIT_LD()     asm volatile("tcgen05.wait::ld.sync.aligned;" ::: "memory")
#define LDTM32(r, addr) \
    asm volatile("tcgen05.ld.sync.aligned.32x32b.x32.b32 " \
        "{%0,%1,%2,%3,%4,%5,%6,%7,%8,%9,%10,%11,%12,%13,%14,%15," \
        "%16,%17,%18,%19,%20,%21,%22,%23,%24,%25,%26,%27,%28,%29,%30,%31}, [%32];" \
        : "=r"((r)[0]),"=r"((r)[1]),"=r"((r)[2]),"=r"((r)[3]),"=r"((r)[4]),"=r"((r)[5]),"=r"((r)[6]),"=r"((r)[7]), \
          "=r"((r)[8]),"=r"((r)[9]),"=r"((r)[10]),"=r"((r)[11]),"=r"((r)[12]),"=r"((r)[13]),"=r"((r)[14]),"=r"((r)[15]), \
          "=r"((r)[16]),"=r"((r)[17]),"=r"((r)[18]),"=r"((r)[19]),"=r"((r)[20]),"=r"((r)[21]),"=r"((r)[22]),"=r"((r)[23]), \
          "=r"((r)[24]),"=r"((r)[25]),"=r"((r)[26]),"=r"((r)[27]),"=r"((r)[28]),"=r"((r)[29]),"=r"((r)[30]),"=r"((r)[31]) \
        : "r"(addr))
#endif

// smem: S1 64KB | S2 64KB | S3/stage 67584 | aux 4KB
#define STAGE_OFF 131072
#define AUX_OFF   (131072 + 128 * TS * 4)
#define SMEMSZ    (AUX_OFF + 4096)

// ================= k_proj: grid 192 = ci*3 + p; p: 0=Q 1=K 2=V+G =================
__global__ void __launch_bounds__(512) k_proj(const float* __restrict__ tokens,
        const float* __restrict__ Wq, const float* __restrict__ Wk,
        const float* __restrict__ Wv, const float* __restrict__ Wg,
        const float* __restrict__ bg,
        const float* __restrict__ g1, const float* __restrict__ b1) {
#if HAS_TC
    extern __shared__ __align__(1024) char smem[];
    uint32_t* S1 = (uint32_t*)smem;
    uint32_t* S2 = (uint32_t*)(smem + 65536);
    uint32_t* S3 = (uint32_t*)(smem + STAGE_OFF);
    float* stage = (float*)(smem + STAGE_OFF);
    char* aux = smem + AUX_OFF;
    uint32_t auxa = smem_u32(aux), mbar = auxa + 8;
    float* bgs = (float*)(aux + 16);
    int tid = threadIdx.x, wid = tid >> 5;
    int ci = blockIdx.x / 3, p = blockIdx.x - ci * 3;

    if (wid == 0) TC_ALLOC(auxa, 256);
    if (tid == 0) MBAR_INIT(mbar, 1);
    if (p == 2 && tid < 128) bgs[tid] = bg[tid];
    __syncthreads();
    uint32_t tmem;
    asm volatile("ld.shared.b32 %0,[%1];" : "=r"(tmem) : "r"(auxa));
    uint32_t D0 = tmem, D1 = tmem + 128;
    uint32_t uS1 = smem_u32(S1), uS2 = smem_u32(S2), uS3 = smem_u32(S3);

    ln512(tokens + (size_t)ci * 16384, stage, g1, b1);
    __syncthreads();
    fill_nt<512>(S1, stage, TS);                                  // X pairs
    fill_t<512>(S2, p == 0 ? Wq : p == 1 ? Wk : Wv, 128);
    FENCE_ASYNC();
    __syncthreads();
    if (p < 2) {
        if (wid == 0) mma_tile3(D0, uS1, uS2, mbar, true, true);
        MBAR_WAIT(mbar, 0); TC_FENCE_AFTER();
        if (tid < 256) {
            int t = tid & 127, wg = tid >> 7;
            uint32_t rr[2][32];
            LDTM32(rr[0], D0 + (wg * 2 + 0) * 32);
            LDTM32(rr[1], D0 + (wg * 2 + 1) * 32);
            TC_WAIT_LD();
            if (p == 0) {   // Qp pairs -> S1 (X no longer needed)
#pragma unroll
                for (int b = 0; b < 2; b++)
#pragma unroll
                    for (int j = 0; j < 32; j += 2) {
                        int c = wg * 64 + b * 32 + j;
                        float f0 = phi_f(__uint_as_float(rr[b][j]));
                        float f1 = phi_f(__uint_as_float(rr[b][j + 1]));
                        uint32_t hi, lo; pair2(f0, f1, hi, lo);
                        uint32_t w = bfoff(t, c) >> 2;
                        S1[w] = hi; S1[8192 + w] = lo;
                    }
            } else {        // Kp fp32 -> stage
#pragma unroll
                for (int b = 0; b < 2; b++)
#pragma unroll
                    for (int j = 0; j < 32; j++)
                        stage[t * TS + wg * 64 + b * 32 + j] = phi_f(__uint_as_float(rr[b][j]));
            }
        }
        __syncthreads();
        if (p == 0) {
            cp64k<512>(g_QpP + (size_t)ci * 16384, S1);
        } else {
            fill_nt<512>(g_KpP + (size_t)ci * 16384, stage, TS);  // gmem-coalesced
            fill_t<512>(S2, stage, TS);                           // KpT pairs -> smem
            if (tid < 128) {
                float s = 0.f;
#pragma unroll 4
                for (int t = 0; t < 128; t++) s += stage[t * TS + tid];
                g_uv[ci * Dm + tid] = s;
            }
            __syncthreads();
            cp64k<512>(g_KpTP + (size_t)ci * 16384, S2);
        }
    } else {
        // V MMA (no commit), then Wg pairs into S3 region, G MMA (commit)
        if (wid == 0) mma_tile3(D0, uS1, uS2, mbar, true, false);
        fill_t<512>(S3, Wg, 128);
        FENCE_ASYNC();
        __syncthreads();
        if (wid == 0) mma_tile3(D1, uS1, uS3, mbar, true, true);
        MBAR_WAIT(mbar, 0); TC_FENCE_AFTER();
        // gate epilogue: Vg = V * sigmoid(G + bg) -> stage (overwrites Wg pairs)
        if (tid < 256) {
            int t = tid & 127, wg = tid >> 7;
#pragma unroll
            for (int b = 0; b < 2; b++) {
                uint32_t rv[32], rg[32];
                LDTM32(rv, D0 + (wg * 2 + b) * 32);
                LDTM32(rg, D1 + (wg * 2 + b) * 32);
                TC_WAIT_LD();
#pragma unroll
                for (int j = 0; j < 32; j++) {
                    int c = wg * 64 + b * 32 + j;
                    stage[t * TS + c] = __uint_as_float(rv[j]) *
                                        sig_f(__uint_as_float(rg[j]) + bgs[c]);
                }
            }
        }
        __syncthreads();
        fill_t<512>(S2, stage, TS);                               // VgT pairs (S2 free)
        __syncthreads();
        cp64k<512>(g_VgTP + (size_t)ci * 16384, S2);
    }
    __syncthreads();
    if (tid == 0) MBAR_INVAL(mbar);
    __syncthreads();
    if (wid == 0) TC_DEALLOC(tmem, 256);
#endif
}

// ================= k_U: Ut = VgT @ KpT^T  (grid 64) =================
__global__ void __launch_bounds__(512) k_U() {
#if HAS_TC
    extern __shared__ __align__(1024) char smem[];
    uint32_t* S1 = (uint32_t*)smem;
    uint32_t* S2 = (uint32_t*)(smem + 65536);
    float* stage = (float*)(smem + STAGE_OFF);
    char* aux = smem + AUX_OFF;
    uint32_t auxa = smem_u32(aux), mbar = auxa + 8;
    int tid = threadIdx.x, wid = tid >> 5, ci = blockIdx.x;

    if (wid == 0) TC_ALLOC(auxa, 256);
    if (tid == 0) MBAR_INIT(mbar, 1);
    __syncthreads();
    uint32_t tmem;
    asm volatile("ld.shared.b32 %0,[%1];" : "=r"(tmem) : "r"(auxa));
    uint32_t uS1 = smem_u32(S1), uS2 = smem_u32(S2);

    cp64k<512>(S1, g_VgTP + (size_t)ci * 16384);
    cp64k<512>(S2, g_KpTP + (size_t)ci * 16384);
    FENCE_ASYNC();
    __syncthreads();
    if (wid == 0) mma_tile3(tmem, uS1, uS2, mbar, true, true);
    MBAR_WAIT(mbar, 0); TC_FENCE_AFTER();
    if (tid < 256) {
        int t = tid & 127, wg = tid >> 7;
        uint32_t rr[2][32];
        LDTM32(rr[0], tmem + (wg * 2 + 0) * 32);
        LDTM32(rr[1], tmem + (wg * 2 + 1) * 32);
        TC_WAIT_LD();
#pragma unroll
        for (int b = 0; b < 2; b++)
#pragma unroll
            for (int j = 0; j < 32; j++)
                stage[t * TS + wg * 64 + b * 32 + j] = __uint_as_float(rr[b][j]);
    }
    __syncthreads();
    stage_out<512>(g_Ut + (size_t)ci * 16384, stage);
    __syncthreads();
    if (tid == 0) MBAR_INVAL(mbar);
    __syncthreads();
    if (wid == 0) TC_DEALLOC(tmem, 256);
#endif
}

// ================= k_prefix: scan Ut -> STP pairs (coalesced) + sv; grid 33 =================
__global__ void __launch_bounds__(256) k_prefix() {
    int bid = blockIdx.x, tid = threadIdx.x;
    if (bid < 32) {
        int b = bid >> 4;                       // 16 CTAs per batch
        int m = (bid & 15) * 8 + (tid >> 5);    // row (8 rows per CTA)
        int lane = tid & 31;
        const float* Ut = g_Ut + (size_t)b * CPB * 16384 + m * 128;
        uint32_t* STP = g_STP + (size_t)b * CPB * 16384;
        uint32_t w0 = bfoff(m, 2 * lane) >> 2;
        uint32_t w1 = bfoff(m, 64 + 2 * lane) >> 2;
        float a0 = 0.f, a1 = 0.f, a2 = 0.f, a3 = 0.f;
#pragma unroll
        for (int c0 = 0; c0 < CPB; c0 += 8) {
            float2 v0[8], v1[8];
#pragma unroll
            for (int j = 0; j < 8; j++) {
                v0[j] = *(const float2*)&Ut[(size_t)(c0 + j) * 16384 + 2 * lane];
                v1[j] = *(const float2*)&Ut[(size_t)(c0 + j) * 16384 + 64 + 2 * lane];
            }
#pragma unroll
            for (int j = 0; j < 8; j++) {
                uint32_t* dst = STP + (size_t)(c0 + j) * 16384;
                uint32_t hi, lo;
                pair2(a0, a1, hi, lo); dst[w0] = hi; dst[8192 + w0] = lo;
                pair2(a2, a3, hi, lo); dst[w1] = hi; dst[8192 + w1] = lo;
                a0 += v0[j].x; a1 += v0[j].y; a2 += v1[j].x; a3 += v1[j].y;
            }
        }
    } else {
        int b = tid >> 7, h = tid & 127;
        float acc = 0.f;
#pragma unroll
        for (int c0 = 0; c0 < CPB; c0 += 8) {
            float v[8];
#pragma unroll
            for (int j = 0; j < 8; j++) v[j] = g_uv[(b * CPB + c0 + j) * Dm + h];
#pragma unroll
            for (int j = 0; j < 8; j++) { g_sv[(b * CPB + c0 + j) * Dm + h] = acc; acc += v[j]; }
        }
    }
}

// ===== k_attn: inter+scores -> mask/denom -> intra -> /denom -> @Wo -> +res -> LN2 =====
__global__ void __launch_bounds__(512) k_attn(const float* __restrict__ tokens,
        const float* __restrict__ Wo, const float* __restrict__ g2,
        const float* __restrict__ b2, float* __restrict__ out) {
#if HAS_TC
    extern __shared__ __align__(1024) char smem[];
    uint32_t* S1 = (uint32_t*)smem;
    uint32_t* S2 = (uint32_t*)(smem + 65536);
    uint32_t* S3 = (uint32_t*)(smem + STAGE_OFF);
    float* T = (float*)(smem + STAGE_OFF);      // fp32 token stage (after intra)
    char* aux = smem + AUX_OFF;
    uint32_t auxa = smem_u32(aux), mbar = auxa + 8;
    float* svs  = (float*)(aux + 16);           // 128
    float* denq = (float*)(aux + 528);          // 256
    float* denp = (float*)(aux + 1552);         // 256
    int tid = threadIdx.x, wid = tid >> 5, ci = blockIdx.x;

    if (wid == 0) TC_ALLOC(auxa, 256);
    if (tid == 0) MBAR_INIT(mbar, 1);
    if (tid < 128) svs[tid] = g_sv[ci * Dm + tid];
    __syncthreads();
    uint32_t tmem;
    asm volatile("ld.shared.b32 %0,[%1];" : "=r"(tmem) : "r"(auxa));
    uint32_t D0 = tmem, D1 = tmem + 128;
    uint32_t uS1 = smem_u32(S1), uS2 = smem_u32(S2), uS3 = smem_u32(S3);

    cp64k<512>(S1, g_QpP + (size_t)ci * 16384);
    cp64k<512>(S2, g_KpP + (size_t)ci * 16384);
    cp64k<512>(S3, g_STP + (size_t)ci * 16384);
    FENCE_ASYNC();
    __syncthreads();
    if (wid == 0) {
        mma_tile3(D0, uS1, uS3, mbar, true, false);     // inter = Qp @ S
        mma_tile3(D1, uS1, uS2, mbar, true, true);      // scores = Qp @ Kp^T
    }
    MBAR_WAIT(mbar, 0); TC_FENCE_AFTER();
    cp64k<512>(S3, g_VgTP + (size_t)ci * 16384);        // Vg^T (S3 free)
    fill_t<512>(S2, Wo, 128);                           // Wo^T pairs (S2 free)
    // denq[t] = Qp[t,:] . sv  (read S1 before overwrite; 256 threads, half cols each)
    if (tid < 256) {
        int t = tid & 127, half = tid >> 7;
        float den = 0.f;
#pragma unroll 4
        for (int cp = 0; cp < 32; cp++) {
            int col = half * 64 + 2 * cp;
            uint32_t w = bfoff(t, col) >> 2;
            float2 h = unpackbf2(S1[w]);
            float2 l = unpackbf2(S1[8192 + w]);
            den += (h.x + l.x) * svs[col] + (h.y + l.y) * svs[col + 1];
        }
        denq[half * 128 + t] = den;
    }
    __syncthreads();
    // mask + partial denom; Amask pairs -> S1
    if (tid < 256) {
        int t = tid & 127, wg = tid >> 7;
        float den = 0.f;
        uint32_t r0[32], r1[32];
        LDTM32(r0, D1 + (wg * 2 + 0) * 32);
        LDTM32(r1, D1 + (wg * 2 + 1) * 32);
        TC_WAIT_LD();
#pragma unroll
        for (int b = 0; b < 2; b++) {
            uint32_t* rr = b ? r1 : r0;
#pragma unroll
            for (int j = 0; j < 32; j += 2) {
                int c = wg * 64 + b * 32 + j;
                float f0 = __uint_as_float(rr[j]);     if (c > t)     f0 = 0.f;
                float f1 = __uint_as_float(rr[j + 1]); if (c + 1 > t) f1 = 0.f;
                den += f0 + f1;
                uint32_t hi, lo; pair2(f0, f1, hi, lo);
                uint32_t w = bfoff(t, c) >> 2;
                S1[w] = hi; S1[8192 + w] = lo;
            }
        }
        denp[wg * 128 + t] = den;
    }
    FENCE_ASYNC(); TC_FENCE_BEFORE();
    __syncthreads();
    if (wid == 0) mma_tile3(D0, uS1, uS3, mbar, false, true);    // D0 += Amask @ Vg
    MBAR_WAIT(mbar, 1); TC_FENCE_AFTER();
    // tokens -> T (S3 free after intra); overlaps divide epilogue below
    {
        const float4* t4 = (const float4*)(tokens + (size_t)ci * 16384);
#pragma unroll
        for (int it = 0; it < 8; it++) {
            int p = tid + it * 512;
            int r = p >> 5, c = (p & 31) * 4;
            *(float4*)&T[r * TS + c] = t4[p];
        }
    }
    // divide epilogue -> At pairs into S1
    if (tid < 256) {
        int t = tid & 127, wg = tid >> 7;
        float inv = 1.f / fmaxf(denq[t] + denq[128 + t] + denp[t] + denp[128 + t], ATT_EPS);
        uint32_t r0[32], r1[32];
        LDTM32(r0, D0 + (wg * 2 + 0) * 32);
        LDTM32(r1, D0 + (wg * 2 + 1) * 32);
        TC_WAIT_LD();
#pragma unroll
        for (int b = 0; b < 2; b++) {
            uint32_t* rr = b ? r1 : r0;
#pragma unroll
            for (int j = 0; j < 32; j += 2) {
                int c = wg * 64 + b * 32 + j;
                float f0 = __uint_as_float(rr[j]) * inv;
                float f1 = __uint_as_float(rr[j + 1]) * inv;
                uint32_t hi, lo; pair2(f0, f1, hi, lo);
                uint32_t w = bfoff(t, c) >> 2;
                S1[w] = hi; S1[8192 + w] = lo;
            }
        }
    }
    FENCE_ASYNC(); TC_FENCE_BEFORE();
    __syncthreads();
    if (wid == 0) mma_tile3(D1, uS1, uS2, mbar, true, true);     // out = At @ Wo
    MBAR_WAIT(mbar, 0); TC_FENCE_AFTER();
    // residual: T += 0.1 * result
    if (tid < 256) {
        int t = tid & 127, wg = tid >> 7;
        uint32_t r0[32], r1[32];
        LDTM32(r0, D1 + (wg * 2 + 0) * 32);
        LDTM32(r1, D1 + (wg * 2 + 1) * 32);
        TC_WAIT_LD();
#pragma unroll
        for (int b = 0; b < 2; b++) {
            uint32_t* rr = b ? r1 : r0;
#pragma unroll
            for (int j = 0; j < 32; j++) {
                int c = wg * 64 + b * 32 + j;
                T[t * TS + c] += 0.1f * __uint_as_float(rr[j]);
            }
        }
    }
    __syncthreads();
    // LN2 -> out
    {
        int lane = tid & 31;
        float4 gg = ((const float4*)g2)[lane], bb = ((const float4*)b2)[lane];
        for (int r = wid; r < 128; r += 16) {
            float4 v = *(const float4*)&T[r * TS + lane * 4];
            float s = v.x + v.y + v.z + v.w;
            float ss = v.x * v.x + v.y * v.y + v.z * v.z + v.w * v.w;
#pragma unroll
            for (int o = 16; o; o >>= 1) {
                s  += __shfl_xor_sync(0xffffffffu, s,  o);
                ss += __shfl_xor_sync(0xffffffffu, ss, o);
            }
            float mu = s * (1.f / 128.f);
            float inv = rsqrtf(ss * (1.f / 128.f) - mu * mu + LN_EPS);
            float4 o4;
            o4.x = (v.x - mu) * inv * gg.x + bb.x;
            o4.y = (v.y - mu) * inv * gg.y + bb.y;
            o4.z = (v.z - mu) * inv * gg.z + bb.z;
            o4.w = (v.w - mu) * inv * gg.w + bb.w;
            *(float4*)&out[((size_t)ci * 128 + r) * 128 + lane * 4] = o4;
        }
    }
    __syncthreads();
    if (tid == 0) MBAR_INVAL(mbar);
    __syncthreads();
    if (wid == 0) TC_DEALLOC(tmem, 256);
#endif
}

extern "C" void kernel_launch(void* const* d_in, const int* in_sizes, int n_in,
                              void* d_out, int out_size) {
    const float* tokens = (const float*)d_in[0];
    const float* Wq = (const float*)d_in[1];
    const float* Wk = (const float*)d_in[2];
    const float* Wv = (const float*)d_in[3];
    const float* Wg = (const float*)d_in[4];
    const float* bg = (const float*)d_in[5];
    const float* Wo = (const float*)d_in[6];
    const float* g1 = (const float*)d_in[7];
    const float* b1 = (const float*)d_in[8];
    const float* g2 = (const float*)d_in[9];
    const float* b2 = (const float*)d_in[10];
    float* out = (float*)d_out;

    cudaFuncSetAttribute(k_proj, cudaFuncAttributeMaxDynamicSharedMemorySize, SMEMSZ);
    cudaFuncSetAttribute(k_U,    cudaFuncAttributeMaxDynamicSharedMemorySize, SMEMSZ);
    cudaFuncSetAttribute(k_attn, cudaFuncAttributeMaxDynamicSharedMemorySize, SMEMSZ);

    k_proj<<<192, 512, SMEMSZ>>>(tokens, Wq, Wk, Wv, Wg, bg, g1, b1);
    k_U<<<64, 512, SMEMSZ>>>();
    k_prefix<<<33, 256>>>();
    k_attn<<<64, 512, SMEMSZ>>>(tokens, Wo, g2, b2, out);
}

// round 13
// speedup vs baseline: 3.1427x; 1.1147x over previous
#include <cuda_runtime.h>
#include <cuda_bf16.h>
#include <math.h>
#include <stdint.h>

#define Dm 128
#define TS 132
#define NCH 64
#define CPB 32
#define LN_EPS 1e-5f
#define ATT_EPS 1e-6f

#if defined(__CUDA_ARCH_FEAT_SM103_ALL) || defined(__CUDA_ARCH_FEAT_SM100_ALL)
#define HAS_TC 1
#else
#define HAS_TC 0
#endif

// pair tiles: u32[16384] = hi plane [0..8191], lo plane [8192..16383]
__device__ uint32_t g_QpP [NCH * 16384];
__device__ uint32_t g_KpP [NCH * 16384];
__device__ uint32_t g_KpTP[NCH * 16384];
__device__ uint32_t g_VgTP[NCH * 16384];
__device__ uint32_t g_STP [NCH * 16384];
__device__ float g_Ut[NCH * 16384];
__device__ float g_uv[NCH * Dm];
__device__ float g_sv[NCH * Dm];

// ================= helpers =================
static __device__ __forceinline__ uint32_t smem_u32(const void* p) {
    uint32_t a;
    asm("{ .reg .u64 t; cvta.to.shared.u64 t, %1; cvt.u32.u64 %0, t; }" : "=r"(a) : "l"(p));
    return a;
}
__device__ __forceinline__ float phi_f(float x) { return x > 0.f ? x + 1.f : __expf(x); }
__device__ __forceinline__ float sig_f(float x) { return 1.f / (1.f + __expf(-x)); }

__device__ __forceinline__ uint32_t bfoff(int row, int col) {
    uint32_t u = (uint32_t)(((row >> 3) + (col >> 6) * 16) * 1024 + (row & 7) * 128 + (col & 63) * 2);
    return u ^ ((u >> 3) & 0x70);
}
__device__ __forceinline__ uint32_t packbf(float a, float b) {
    __nv_bfloat16 ha = __float2bfloat16(a), hb = __float2bfloat16(b);
    return (uint32_t)__bfloat16_as_ushort(ha) | ((uint32_t)__bfloat16_as_ushort(hb) << 16);
}
__device__ __forceinline__ void pair2(float a, float b, uint32_t& hi, uint32_t& lo) {
    float ra = __bfloat162float(__float2bfloat16(a));
    float rb = __bfloat162float(__float2bfloat16(b));
    hi = packbf(a, b);
    lo = packbf(a - ra, b - rb);
}
__device__ __forceinline__ float2 unpackbf2(uint32_t u) {
    __nv_bfloat162 v = *reinterpret_cast<__nv_bfloat162*>(&u);
    return __bfloat1622float2(v);
}

template<int NT>
__device__ __forceinline__ void fill_nt(uint32_t* __restrict__ dst, const float* __restrict__ src, int ld) {
    int tid = threadIdx.x;
#pragma unroll
    for (int it = 0; it < 8192 / NT; it++) {
        int p = tid + it * NT;
        int r = p >> 6, c = (p & 63) * 2;
        float2 v = *(const float2*)&src[r * ld + c];
        uint32_t hi, lo; pair2(v.x, v.y, hi, lo);
        uint32_t w = bfoff(r, c) >> 2;
        dst[w] = hi; dst[8192 + w] = lo;
    }
}
template<int NT>
__device__ __forceinline__ void fill_t(uint32_t* __restrict__ dst, const float* __restrict__ src, int ld) {
    int tid = threadIdx.x;
#pragma unroll
    for (int it = 0; it < 8192 / NT; it++) {
        int p = tid + it * NT;
        int n = p & 127, k = (p >> 7) * 2;
        float f0 = src[k * ld + n];
        float f1 = src[(k + 1) * ld + n];
        uint32_t hi, lo; pair2(f0, f1, hi, lo);
        uint32_t w = bfoff(n, k) >> 2;
        dst[w] = hi; dst[8192 + w] = lo;
    }
}
template<int NT>
__device__ __forceinline__ void cp64k(void* __restrict__ dst, const void* __restrict__ src) {
    float4* d = (float4*)dst; const float4* s = (const float4*)src;
    int tid = threadIdx.x;
#pragma unroll
    for (int it = 0; it < 4096 / NT; it++) d[tid + it * NT] = s[tid + it * NT];
}
template<int NT>
__device__ __forceinline__ void stage_out(float* __restrict__ g, const float* __restrict__ stage) {
    int tid = threadIdx.x;
#pragma unroll
    for (int it = 0; it < 4096 / NT; it++) {
        int p = tid + it * NT;
        int r = p >> 5, c = (p & 31) * 4;
        *(float4*)&g[r * 128 + c] = *(const float4*)&stage[r * TS + c];
    }
}
__device__ __forceinline__ void ln512(const float* __restrict__ tok, float* __restrict__ buf,
                                      const float* __restrict__ g1, const float* __restrict__ b1) {
    int lane = threadIdx.x & 31, wid = threadIdx.x >> 5;
    float4 gg = ((const float4*)g1)[lane], bb = ((const float4*)b1)[lane];
    for (int r = wid; r < 128; r += 16) {
        float4 v = ((const float4*)(tok + r * 128))[lane];
        float s = v.x + v.y + v.z + v.w;
        float ss = v.x * v.x + v.y * v.y + v.z * v.z + v.w * v.w;
#pragma unroll
        for (int o = 16; o; o >>= 1) {
            s  += __shfl_xor_sync(0xffffffffu, s,  o);
            ss += __shfl_xor_sync(0xffffffffu, ss, o);
        }
        float mu = s * (1.f / 128.f);
        float inv = rsqrtf(ss * (1.f / 128.f) - mu * mu + LN_EPS);
        float* d = &buf[r * TS + lane * 4];
        d[0] = (v.x - mu) * inv * gg.x + bb.x;
        d[1] = (v.y - mu) * inv * gg.y + bb.y;
        d[2] = (v.z - mu) * inv * gg.z + bb.z;
        d[3] = (v.w - mu) * inv * gg.w + bb.w;
    }
}

// ================= tcgen05 plumbing =================
static __device__ __forceinline__ bool elect1() {
    uint32_t p;
    asm volatile("{ .reg .pred p; elect.sync _|p, 0xFFFFFFFF; selp.b32 %0, 1, 0, p; }" : "=r"(p));
    return p != 0;
}
#define IDESC_F16 ((1u<<4)|(1u<<7)|(1u<<10)|(16u<<17)|(8u<<24))
__device__ __forceinline__ uint64_t mkdesc(uint32_t addr) {
    return ((uint64_t)2 << 61) | ((uint64_t)1 << 46) | ((uint64_t)64 << 32) | ((uint64_t)1 << 16)
         | ((uint64_t)(addr >> 4) & 0x3FFF);
}
#if HAS_TC
__device__ __forceinline__ void mma_ss(uint32_t d, uint64_t ad, uint64_t bd, uint32_t en) {
    asm volatile("{\n\t.reg .pred p;\n\tsetp.ne.u32 p, %4, 0;\n\t"
        "tcgen05.mma.cta_group::1.kind::f16 [%0], %1, %2, %3, {%5,%5,%5,%5}, p;\n\t}"
        :: "r"(d), "l"(ad), "l"(bd), "r"(IDESC_F16), "r"(en), "r"(0u) : "memory");
}
__device__ __forceinline__ void mma_tile3(uint32_t d, uint32_t a_addr, uint32_t b_addr,
                                          uint32_t mbar, bool fresh, bool commit) {
    if (elect1()) {
        uint64_t adb = mkdesc(a_addr), bdb = mkdesc(b_addr);
#pragma unroll
        for (int t = 0; t < 3; t++) {
            uint64_t ao = adb + (t == 2 ? 2048 : 0);
            uint64_t bo = bdb + (t == 1 ? 2048 : 0);
#pragma unroll
            for (int s = 0; s < 8; s++) {
                uint64_t off = (uint64_t)((s >> 2) * 1024 + (s & 3) * 2);
                mma_ss(d, ao + off, bo + off, (t == 0 && s == 0 && fresh) ? 0u : 1u);
            }
        }
        if (commit)
            asm volatile("tcgen05.commit.cta_group::1.mbarrier::arrive::one.shared::cluster.b64 [%0];"
                         :: "r"(mbar) : "memory");
    }
}
#define MBAR_INIT(a, c) asm volatile("mbarrier.init.shared.b64 [%0], %1;" :: "r"(a), "r"(c) : "memory")
#define MBAR_INVAL(a)   asm volatile("mbarrier.inval.shared.b64 [%0];" :: "r"(a) : "memory")
#define MBAR_WAIT(a, par) do { uint32_t _m=(a), _p=(par); \
    asm volatile("{\n\t.reg .pred P1;\n\tWL%=:\n\t" \
        "mbarrier.try_wait.parity.acquire.cta.shared::cta.b64 P1, [%0], %1, 0x989680;\n\t" \
        "@P1 bra.uni WD%=;\n\tbra.uni WL%=;\n\tWD%=:\n\t}" :: "r"(_m), "r"(_p) : "memory"); } while(0)
#define TC_ALLOC(a, n)   asm volatile("tcgen05.alloc.cta_group::1.sync.aligned.shared::cta.b32 [%0], %1;" :: "r"(a), "r"(n) : "memory")
#define TC_DEALLOC(t, n) asm volatile("tcgen05.dealloc.cta_group::1.sync.aligned.b32 %0, %1;" :: "r"(t), "r"(n))
#define TC_FENCE_AFTER()  asm volatile("tcgen05.fence::after_thread_sync;" ::: "memory")
#define TC_FENCE_BEFORE() asm volatile("tcgen05.fence::before_thread_sync;" ::: "memory")
#define FENCE_ASYNC()    asm volatile("fence.proxy.async.shared::cta;" ::: "memory")
#define TC_WAIT_LD()     asm volatile("tcgen05.wait::ld.sync.aligned;" ::: "memory")
#define LDTM32(r, addr) \
    asm volatile("tcgen05.ld.sync.aligned.32x32b.x32.b32 " \
        "{%0,%1,%2,%3,%4,%5,%6,%7,%8,%9,%10,%11,%12,%13,%14,%15," \
        "%16,%17,%18,%19,%20,%21,%22,%23,%24,%25,%26,%27,%28,%29,%30,%31}, [%32];" \
        : "=r"((r)[0]),"=r"((r)[1]),"=r"((r)[2]),"=r"((r)[3]),"=r"((r)[4]),"=r"((r)[5]),"=r"((r)[6]),"=r"((r)[7]), \
          "=r"((r)[8]),"=r"((r)[9]),"=r"((r)[10]),"=r"((r)[11]),"=r"((r)[12]),"=r"((r)[13]),"=r"((r)[14]),"=r"((r)[15]), \
          "=r"((r)[16]),"=r"((r)[17]),"=r"((r)[18]),"=r"((r)[19]),"=r"((r)[20]),"=r"((r)[21]),"=r"((r)[22]),"=r"((r)[23]), \
          "=r"((r)[24]),"=r"((r)[25]),"=r"((r)[26]),"=r"((r)[27]),"=r"((r)[28]),"=r"((r)[29]),"=r"((r)[30]),"=r"((r)[31]) \
        : "r"(addr))
#endif

// smem: S1 64KB | S2 64KB | S3/stage 67584 | aux 4KB
#define STAGE_OFF 131072
#define AUX_OFF   (131072 + 128 * TS * 4)
#define SMEMSZ    (AUX_OFF + 4096)

// ============ k_proj: grid 128 = ci*2 + p; p=0: Q+V+G, p=1: K ============
__global__ void __launch_bounds__(512) k_proj(const float* __restrict__ tokens,
        const float* __restrict__ Wq, const float* __restrict__ Wk,
        const float* __restrict__ Wv, const float* __restrict__ Wg,
        const float* __restrict__ bg,
        const float* __restrict__ g1, const float* __restrict__ b1) {
#if HAS_TC
    extern __shared__ __align__(1024) char smem[];
    uint32_t* S1 = (uint32_t*)smem;
    uint32_t* S2 = (uint32_t*)(smem + 65536);
    uint32_t* S3 = (uint32_t*)(smem + STAGE_OFF);
    float* stage = (float*)(smem + STAGE_OFF);
    char* aux = smem + AUX_OFF;
    uint32_t auxa = smem_u32(aux), mA = auxa + 8, mB = auxa + 16;
    float* bgs = (float*)(aux + 32);
    int tid = threadIdx.x, wid = tid >> 5;
    int ci = blockIdx.x >> 1, p = blockIdx.x & 1;

    if (wid == 0) TC_ALLOC(auxa, 512);
    if (tid == 0) { MBAR_INIT(mA, 1); MBAR_INIT(mB, 1); }
    if (p == 0 && tid < 128) bgs[tid] = bg[tid];
    __syncthreads();
    uint32_t tmem;
    asm volatile("ld.shared.b32 %0,[%1];" : "=r"(tmem) : "r"(auxa));
    uint32_t D0 = tmem, D1 = tmem + 128, D2 = tmem + 256;
    uint32_t uS1 = smem_u32(S1), uS2 = smem_u32(S2), uS3 = smem_u32(S3);

    ln512(tokens + (size_t)ci * 16384, stage, g1, b1);
    __syncthreads();
    fill_nt<512>(S1, stage, TS);                 // X pairs
    fill_t<512>(S2, p == 0 ? Wq : Wk, 128);
    __syncthreads();                             // X fp32 fully consumed
    if (p == 0) {
        fill_t<512>(S3, Wv, 128);                // Wv pairs (overwrites stage)
        FENCE_ASYNC();
        __syncthreads();
        if (wid == 0) {
            mma_tile3(D0, uS1, uS2, mA, true, true);     // Q -> mA flip 1
            mma_tile3(D1, uS1, uS3, mB, true, true);     // V -> mB flip 1
        }
        MBAR_WAIT(mA, 0); TC_FENCE_AFTER();              // Q done, S2 free
        fill_t<512>(S2, Wg, 128);
        FENCE_ASYNC(); TC_FENCE_BEFORE();
        __syncthreads();
        if (wid == 0) mma_tile3(D2, uS1, uS2, mA, true, true);   // G -> mA flip 2
        MBAR_WAIT(mB, 0); TC_FENCE_AFTER();              // V done, S3 free
        // Qp epilogue -> pairs -> S3 (overlaps G MMA)
        if (tid < 256) {
            int t = tid & 127, wg = tid >> 7;
            uint32_t rr[2][32];
            LDTM32(rr[0], D0 + (wg * 2 + 0) * 32);
            LDTM32(rr[1], D0 + (wg * 2 + 1) * 32);
            TC_WAIT_LD();
#pragma unroll
            for (int b = 0; b < 2; b++)
#pragma unroll
                for (int j = 0; j < 32; j += 2) {
                    int c = wg * 64 + b * 32 + j;
                    float f0 = phi_f(__uint_as_float(rr[b][j]));
                    float f1 = phi_f(__uint_as_float(rr[b][j + 1]));
                    uint32_t hi, lo; pair2(f0, f1, hi, lo);
                    uint32_t w = bfoff(t, c) >> 2;
                    S3[w] = hi; S3[8192 + w] = lo;
                }
        }
        __syncthreads();
        cp64k<512>(g_QpP + (size_t)ci * 16384, S3);
        MBAR_WAIT(mA, 1); TC_FENCE_AFTER();              // G done
        __syncthreads();
        // gate epilogue: Vg = V * sigmoid(G + bg) -> stage fp32
        if (tid < 256) {
            int t = tid & 127, wg = tid >> 7;
#pragma unroll
            for (int b = 0; b < 2; b++) {
                uint32_t rv[32], rg[32];
                LDTM32(rv, D1 + (wg * 2 + b) * 32);
                LDTM32(rg, D2 + (wg * 2 + b) * 32);
                TC_WAIT_LD();
#pragma unroll
                for (int j = 0; j < 32; j++) {
                    int c = wg * 64 + b * 32 + j;
                    stage[t * TS + c] = __uint_as_float(rv[j]) *
                                        sig_f(__uint_as_float(rg[j]) + bgs[c]);
                }
            }
        }
        __syncthreads();
        fill_t<512>(S1, stage, TS);                      // VgT pairs
        __syncthreads();
        cp64k<512>(g_VgTP + (size_t)ci * 16384, S1);
    } else {
        FENCE_ASYNC();
        __syncthreads();
        if (wid == 0) mma_tile3(D0, uS1, uS2, mA, true, true);  // K
        MBAR_WAIT(mA, 0); TC_FENCE_AFTER();
        if (tid < 256) {
            int t = tid & 127, wg = tid >> 7;
            uint32_t rr[2][32];
            LDTM32(rr[0], D0 + (wg * 2 + 0) * 32);
            LDTM32(rr[1], D0 + (wg * 2 + 1) * 32);
            TC_WAIT_LD();
#pragma unroll
            for (int b = 0; b < 2; b++)
#pragma unroll
                for (int j = 0; j < 32; j++)
                    stage[t * TS + wg * 64 + b * 32 + j] = phi_f(__uint_as_float(rr[b][j]));
        }
        __syncthreads();
        fill_nt<512>(g_KpP + (size_t)ci * 16384, stage, TS);   // coalesced gmem
        fill_t<512>(S2, stage, TS);                            // KpT pairs -> smem
        if (tid < 128) {
            float s = 0.f;
#pragma unroll 4
            for (int t = 0; t < 128; t++) s += stage[t * TS + tid];
            g_uv[ci * Dm + tid] = s;
        }
        __syncthreads();
        cp64k<512>(g_KpTP + (size_t)ci * 16384, S2);
    }
    __syncthreads();
    if (tid == 0) { MBAR_INVAL(mA); MBAR_INVAL(mB); }
    __syncthreads();
    if (wid == 0) TC_DEALLOC(tmem, 512);
#endif
}

// ================= k_U: Ut = VgT @ KpT^T  (grid 64) =================
__global__ void __launch_bounds__(512) k_U() {
#if HAS_TC
    extern __shared__ __align__(1024) char smem[];
    uint32_t* S1 = (uint32_t*)smem;
    uint32_t* S2 = (uint32_t*)(smem + 65536);
    float* stage = (float*)(smem + STAGE_OFF);
    char* aux = smem + AUX_OFF;
    uint32_t auxa = smem_u32(aux), mA = auxa + 8;
    int tid = threadIdx.x, wid = tid >> 5, ci = blockIdx.x;

    cp64k<512>(S1, g_VgTP + (size_t)ci * 16384);
    cp64k<512>(S2, g_KpTP + (size_t)ci * 16384);
    if (wid == 0) TC_ALLOC(auxa, 256);
    if (tid == 0) MBAR_INIT(mA, 1);
    FENCE_ASYNC();
    __syncthreads();
    uint32_t tmem;
    asm volatile("ld.shared.b32 %0,[%1];" : "=r"(tmem) : "r"(auxa));
    if (wid == 0) mma_tile3(tmem, smem_u32(S1), smem_u32(S2), mA, true, true);
    MBAR_WAIT(mA, 0); TC_FENCE_AFTER();
    if (tid < 256) {
        int t = tid & 127, wg = tid >> 7;
        uint32_t rr[2][32];
        LDTM32(rr[0], tmem + (wg * 2 + 0) * 32);
        LDTM32(rr[1], tmem + (wg * 2 + 1) * 32);
        TC_WAIT_LD();
#pragma unroll
        for (int b = 0; b < 2; b++)
#pragma unroll
            for (int j = 0; j < 32; j++)
                stage[t * TS + wg * 64 + b * 32 + j] = __uint_as_float(rr[b][j]);
    }
    __syncthreads();
    stage_out<512>(g_Ut + (size_t)ci * 16384, stage);
    __syncthreads();
    if (tid == 0) MBAR_INVAL(mA);
    __syncthreads();
    if (wid == 0) TC_DEALLOC(tmem, 256);
#endif
}

// ======== k_prefix: scan Ut -> STP pairs (coalesced) + sv; grid 33 ========
__global__ void __launch_bounds__(256) k_prefix() {
    int bid = blockIdx.x, tid = threadIdx.x;
    if (bid < 32) {
        int b = bid >> 4;
        int m = (bid & 15) * 8 + (tid >> 5);
        int lane = tid & 31;
        const float* Ut = g_Ut + (size_t)b * CPB * 16384 + m * 128;
        uint32_t* STP = g_STP + (size_t)b * CPB * 16384;
        uint32_t w0 = bfoff(m, 2 * lane) >> 2;
        uint32_t w1 = bfoff(m, 64 + 2 * lane) >> 2;
        float a0 = 0.f, a1 = 0.f, a2 = 0.f, a3 = 0.f;
#pragma unroll
        for (int c0 = 0; c0 < CPB; c0 += 8) {
            float2 v0[8], v1[8];
#pragma unroll
            for (int j = 0; j < 8; j++) {
                v0[j] = *(const float2*)&Ut[(size_t)(c0 + j) * 16384 + 2 * lane];
                v1[j] = *(const float2*)&Ut[(size_t)(c0 + j) * 16384 + 64 + 2 * lane];
            }
#pragma unroll
            for (int j = 0; j < 8; j++) {
                uint32_t* dst = STP + (size_t)(c0 + j) * 16384;
                uint32_t hi, lo;
                pair2(a0, a1, hi, lo); dst[w0] = hi; dst[8192 + w0] = lo;
                pair2(a2, a3, hi, lo); dst[w1] = hi; dst[8192 + w1] = lo;
                a0 += v0[j].x; a1 += v0[j].y; a2 += v1[j].x; a3 += v1[j].y;
            }
        }
    } else {
        int b = tid >> 7, h = tid & 127;
        float acc = 0.f;
#pragma unroll
        for (int c0 = 0; c0 < CPB; c0 += 8) {
            float v[8];
#pragma unroll
            for (int j = 0; j < 8; j++) v[j] = g_uv[(b * CPB + c0 + j) * Dm + h];
#pragma unroll
            for (int j = 0; j < 8; j++) { g_sv[(b * CPB + c0 + j) * Dm + h] = acc; acc += v[j]; }
        }
    }
}

// ===== k_attn: overlapped chain with 2 mbarriers; grid 64 =====
__global__ void __launch_bounds__(512) k_attn(const float* __restrict__ tokens,
        const float* __restrict__ Wo, const float* __restrict__ g2,
        const float* __restrict__ b2, float* __restrict__ out) {
#if HAS_TC
    extern __shared__ __align__(1024) char smem[];
    uint32_t* S1 = (uint32_t*)smem;
    uint32_t* S2 = (uint32_t*)(smem + 65536);
    uint32_t* S3 = (uint32_t*)(smem + STAGE_OFF);
    float* T = (float*)(smem + STAGE_OFF);
    char* aux = smem + AUX_OFF;
    uint32_t auxa = smem_u32(aux), mA = auxa + 8, mB = auxa + 16;
    float* svs  = (float*)(aux + 32);
    float* denq = (float*)(aux + 544);
    float* denp = (float*)(aux + 1568);
    int tid = threadIdx.x, wid = tid >> 5, ci = blockIdx.x;

    cp64k<512>(S1, g_QpP + (size_t)ci * 16384);
    cp64k<512>(S2, g_KpP + (size_t)ci * 16384);
    cp64k<512>(S3, g_STP + (size_t)ci * 16384);
    if (wid == 0) TC_ALLOC(auxa, 256);
    if (tid == 0) { MBAR_INIT(mA, 1); MBAR_INIT(mB, 1); }
    if (tid < 128) svs[tid] = g_sv[ci * Dm + tid];
    FENCE_ASYNC();
    __syncthreads();
    uint32_t tmem;
    asm volatile("ld.shared.b32 %0,[%1];" : "=r"(tmem) : "r"(auxa));
    uint32_t D0 = tmem, D1 = tmem + 128;
    uint32_t uS1 = smem_u32(S1), uS2 = smem_u32(S2), uS3 = smem_u32(S3);

    if (wid == 0) {
        mma_tile3(D1, uS1, uS2, mA, true, true);      // scores -> mA flip 1
        mma_tile3(D0, uS1, uS3, mB, true, true);      // inter  -> mB flip 1
    }
    MBAR_WAIT(mA, 0); TC_FENCE_AFTER();               // scores done, S2 free
    // threads 0-255: mask epi (D1 -> Amask pairs -> S2); 256-511: denq
    if (tid < 256) {
        int t = tid & 127, wg = tid >> 7;
        float den = 0.f;
        uint32_t r0[32], r1[32];
        LDTM32(r0, D1 + (wg * 2 + 0) * 32);
        LDTM32(r1, D1 + (wg * 2 + 1) * 32);
        TC_WAIT_LD();
#pragma unroll
        for (int b = 0; b < 2; b++) {
            uint32_t* rr = b ? r1 : r0;
#pragma unroll
            for (int j = 0; j < 32; j += 2) {
                int c = wg * 64 + b * 32 + j;
                float f0 = __uint_as_float(rr[j]);     if (c > t)     f0 = 0.f;
                float f1 = __uint_as_float(rr[j + 1]); if (c + 1 > t) f1 = 0.f;
                den += f0 + f1;
                uint32_t hi, lo; pair2(f0, f1, hi, lo);
                uint32_t w = bfoff(t, c) >> 2;
                S2[w] = hi; S2[8192 + w] = lo;
            }
        }
        denp[wg * 128 + t] = den;
    } else {
        int q = tid - 256;
        int t = q & 127, half = q >> 7;
        float den = 0.f;
#pragma unroll 4
        for (int cp = 0; cp < 32; cp++) {
            int col = half * 64 + 2 * cp;
            uint32_t w = bfoff(t, col) >> 2;
            float2 h = unpackbf2(S1[w]);
            float2 l = unpackbf2(S1[8192 + w]);
            den += (h.x + l.x) * svs[col] + (h.y + l.y) * svs[col + 1];
        }
        denq[half * 128 + t] = den;
    }
    __syncthreads();
    MBAR_WAIT(mB, 0); TC_FENCE_AFTER();               // inter done: S1, S3 free
    cp64k<512>(S3, g_VgTP + (size_t)ci * 16384);      // Vg^T pairs
    fill_t<512>(S1, Wo, 128);                         // Wo^T pairs
    FENCE_ASYNC(); TC_FENCE_BEFORE();
    __syncthreads();
    if (wid == 0) mma_tile3(D0, uS2, uS3, mA, false, true);   // intra -> mA flip 2
    MBAR_WAIT(mA, 1); TC_FENCE_AFTER();               // intra done: S3 free
    // tokens -> T (overlaps divide epilogue below)
    {
        const float4* t4 = (const float4*)(tokens + (size_t)ci * 16384);
#pragma unroll
        for (int it = 0; it < 8; it++) {
            int p = tid + it * 512;
            int r = p >> 5, c = (p & 31) * 4;
            *(float4*)&T[r * TS + c] = t4[p];
        }
    }
    // divide epilogue -> At pairs -> S2 (Amask dead after intra)
    if (tid < 256) {
        int t = tid & 127, wg = tid >> 7;
        float inv = 1.f / fmaxf(denq[t] + denq[128 + t] + denp[t] + denp[128 + t], ATT_EPS);
        uint32_t r0[32], r1[32];
        LDTM32(r0, D0 + (wg * 2 + 0) * 32);
        LDTM32(r1, D0 + (wg * 2 + 1) * 32);
        TC_WAIT_LD();
#pragma unroll
        for (int b = 0; b < 2; b++) {
            uint32_t* rr = b ? r1 : r0;
#pragma unroll
            for (int j = 0; j < 32; j += 2) {
                int c = wg * 64 + b * 32 + j;
                float f0 = __uint_as_float(rr[j]) * inv;
                float f1 = __uint_as_float(rr[j + 1]) * inv;
                uint32_t hi, lo; pair2(f0, f1, hi, lo);
                uint32_t w = bfoff(t, c) >> 2;
                S2[w] = hi; S2[8192 + w] = lo;
            }
        }
    }
    FENCE_ASYNC(); TC_FENCE_BEFORE();
    __syncthreads();
    if (wid == 0) mma_tile3(D1, uS2, uS1, mB, true, true);    // At @ Wo -> mB flip 2
    MBAR_WAIT(mB, 1); TC_FENCE_AFTER();
    // residual: T += 0.1 * result
    if (tid < 256) {
        int t = tid & 127, wg = tid >> 7;
        uint32_t r0[32], r1[32];
        LDTM32(r0, D1 + (wg * 2 + 0) * 32);
        LDTM32(r1, D1 + (wg * 2 + 1) * 32);
        TC_WAIT_LD();
#pragma unroll
        for (int b = 0; b < 2; b++) {
            uint32_t* rr = b ? r1 : r0;
#pragma unroll
            for (int j = 0; j < 32; j++) {
                int c = wg * 64 + b * 32 + j;
                T[t * TS + c] += 0.1f * __uint_as_float(rr[j]);
            }
        }
    }
    __syncthreads();
    // LN2 -> out
    {
        int lane = tid & 31;
        float4 gg = ((const float4*)g2)[lane], bb = ((const float4*)b2)[lane];
        for (int r = wid; r < 128; r += 16) {
            float4 v = *(const float4*)&T[r * TS + lane * 4];
            float s = v.x + v.y + v.z + v.w;
            float ss = v.x * v.x + v.y * v.y + v.z * v.z + v.w * v.w;
#pragma unroll
            for (int o = 16; o; o >>= 1) {
                s  += __shfl_xor_sync(0xffffffffu, s,  o);
                ss += __shfl_xor_sync(0xffffffffu, ss, o);
            }
            float mu = s * (1.f / 128.f);
            float inv = rsqrtf(ss * (1.f / 128.f) - mu * mu + LN_EPS);
            float4 o4;
            o4.x = (v.x - mu) * inv * gg.x + bb.x;
            o4.y = (v.y - mu) * inv * gg.y + bb.y;
            o4.z = (v.z - mu) * inv * gg.z + bb.z;
            o4.w = (v.w - mu) * inv * gg.w + bb.w;
            *(float4*)&out[((size_t)ci * 128 + r) * 128 + lane * 4] = o4;
        }
    }
    __syncthreads();
    if (tid == 0) { MBAR_INVAL(mA); MBAR_INVAL(mB); }
    __syncthreads();
    if (wid == 0) TC_DEALLOC(tmem, 256);
#endif
}

extern "C" void kernel_launch(void* const* d_in, const int* in_sizes, int n_in,
                              void* d_out, int out_size) {
    const float* tokens = (const float*)d_in[0];
    const float* Wq = (const float*)d_in[1];
    const float* Wk = (const float*)d_in[2];
    const float* Wv = (const float*)d_in[3];
    const float* Wg = (const float*)d_in[4];
    const float* bg = (const float*)d_in[5];
    const float* Wo = (const float*)d_in[6];
    const float* g1 = (const float*)d_in[7];
    const float* b1 = (const float*)d_in[8];
    const float* g2 = (const float*)d_in[9];
    const float* b2 = (const float*)d_in[10];
    float* out = (float*)d_out;

    cudaFuncSetAttribute(k_proj, cudaFuncAttributeMaxDynamicSharedMemorySize, SMEMSZ);
    cudaFuncSetAttribute(k_U,    cudaFuncAttributeMaxDynamicSharedMemorySize, SMEMSZ);
    cudaFuncSetAttribute(k_attn, cudaFuncAttributeMaxDynamicSharedMemorySize, SMEMSZ);

    k_proj<<<128, 512, SMEMSZ>>>(tokens, Wq, Wk, Wv, Wg, bg, g1, b1);
    k_U<<<64, 512, SMEMSZ>>>();
    k_prefix<<<33, 256>>>();
    k_attn<<<64, 512, SMEMSZ>>>(tokens, Wo, g2, b2, out);
}

// round 17
// speedup vs baseline: 3.2297x; 1.0277x over previous
#include <cuda_runtime.h>
#include <cuda_bf16.h>
#include <math.h>
#include <stdint.h>

#define Dm 128
#define TS 132
#define NCH 64
#define CPB 32
#define LN_EPS 1e-5f
#define ATT_EPS 1e-6f

#if defined(__CUDA_ARCH_FEAT_SM103_ALL) || defined(__CUDA_ARCH_FEAT_SM100_ALL)
#define HAS_TC 1
#else
#define HAS_TC 0
#endif

// pair tiles: u32[16384] = hi plane [0..8191], lo plane [8192..16383]
__device__ uint32_t g_QpP [NCH * 16384];
__device__ uint32_t g_KpP [NCH * 16384];
__device__ uint32_t g_VgTP[NCH * 16384];
__device__ uint32_t g_STP [NCH * 16384];
__device__ float g_Ut[NCH * 16384];
__device__ float g_uv[NCH * Dm];
__device__ float g_sv[NCH * Dm];

// ================= helpers =================
static __device__ __forceinline__ uint32_t smem_u32(const void* p) {
    uint32_t a;
    asm("{ .reg .u64 t; cvta.to.shared.u64 t, %1; cvt.u32.u64 %0, t; }" : "=r"(a) : "l"(p));
    return a;
}
__device__ __forceinline__ float phi_f(float x) { return x > 0.f ? x + 1.f : __expf(x); }
__device__ __forceinline__ float sig_f(float x) { return 1.f / (1.f + __expf(-x)); }

__device__ __forceinline__ uint32_t bfoff(int row, int col) {
    uint32_t u = (uint32_t)(((row >> 3) + (col >> 6) * 16) * 1024 + (row & 7) * 128 + (col & 63) * 2);
    return u ^ ((u >> 3) & 0x70);
}
__device__ __forceinline__ uint32_t packbf(float a, float b) {
    __nv_bfloat16 ha = __float2bfloat16(a), hb = __float2bfloat16(b);
    return (uint32_t)__bfloat16_as_ushort(ha) | ((uint32_t)__bfloat16_as_ushort(hb) << 16);
}
__device__ __forceinline__ void pair2(float a, float b, uint32_t& hi, uint32_t& lo) {
    float ra = __bfloat162float(__float2bfloat16(a));
    float rb = __bfloat162float(__float2bfloat16(b));
    hi = packbf(a, b);
    lo = packbf(a - ra, b - rb);
}
__device__ __forceinline__ float2 unpackbf2(uint32_t u) {
    __nv_bfloat162 v = *reinterpret_cast<__nv_bfloat162*>(&u);
    return __bfloat1622float2(v);
}

template<int NT>
__device__ __forceinline__ void fill_nt(uint32_t* __restrict__ dst, const float* __restrict__ src, int ld) {
    int tid = threadIdx.x;
#pragma unroll
    for (int it = 0; it < 8192 / NT; it++) {
        int p = tid + it * NT;
        int r = p >> 6, c = (p & 63) * 2;
        float2 v = *(const float2*)&src[r * ld + c];
        uint32_t hi, lo; pair2(v.x, v.y, hi, lo);
        uint32_t w = bfoff(r, c) >> 2;
        dst[w] = hi; dst[8192 + w] = lo;
    }
}
template<int NT>
__device__ __forceinline__ void fill_t(uint32_t* __restrict__ dst, const float* __restrict__ src, int ld) {
    int tid = threadIdx.x;
#pragma unroll
    for (int it = 0; it < 8192 / NT; it++) {
        int p = tid + it * NT;
        int n = p & 127, k = (p >> 7) * 2;
        float f0 = src[k * ld + n];
        float f1 = src[(k + 1) * ld + n];
        uint32_t hi, lo; pair2(f0, f1, hi, lo);
        uint32_t w = bfoff(n, k) >> 2;
        dst[w] = hi; dst[8192 + w] = lo;
    }
}
template<int NT>
__device__ __forceinline__ void cp64k(void* __restrict__ dst, const void* __restrict__ src) {
    float4* d = (float4*)dst; const float4* s = (const float4*)src;
    int tid = threadIdx.x;
#pragma unroll
    for (int it = 0; it < 4096 / NT; it++) d[tid + it * NT] = s[tid + it * NT];
}
template<int NT>
__device__ __forceinline__ void stage_out(float* __restrict__ g, const float* __restrict__ stage) {
    int tid = threadIdx.x;
#pragma unroll
    for (int it = 0; it < 4096 / NT; it++) {
        int p = tid + it * NT;
        int r = p >> 5, c = (p & 31) * 4;
        *(float4*)&g[r * 128 + c] = *(const float4*)&stage[r * TS + c];
    }
}
__device__ __forceinline__ void ln512(const float* __restrict__ tok, float* __restrict__ buf,
                                      const float* __restrict__ g1, const float* __restrict__ b1) {
    int lane = threadIdx.x & 31, wid = threadIdx.x >> 5;
    float4 gg = ((const float4*)g1)[lane], bb = ((const float4*)b1)[lane];
    for (int r = wid; r < 128; r += 16) {
        float4 v = ((const float4*)(tok + r * 128))[lane];
        float s = v.x + v.y + v.z + v.w;
        float ss = v.x * v.x + v.y * v.y + v.z * v.z + v.w * v.w;
#pragma unroll
        for (int o = 16; o; o >>= 1) {
            s  += __shfl_xor_sync(0xffffffffu, s,  o);
            ss += __shfl_xor_sync(0xffffffffu, ss, o);
        }
        float mu = s * (1.f / 128.f);
        float inv = rsqrtf(ss * (1.f / 128.f) - mu * mu + LN_EPS);
        float* d = &buf[r * TS + lane * 4];
        d[0] = (v.x - mu) * inv * gg.x + bb.x;
        d[1] = (v.y - mu) * inv * gg.y + bb.y;
        d[2] = (v.z - mu) * inv * gg.z + bb.z;
        d[3] = (v.w - mu) * inv * gg.w + bb.w;
    }
}

// ================= tcgen05 plumbing =================
static __device__ __forceinline__ bool elect1() {
    uint32_t p;
    asm volatile("{ .reg .pred p; elect.sync _|p, 0xFFFFFFFF; selp.b32 %0, 1, 0, p; }" : "=r"(p));
    return p != 0;
}
#define IDESC_F16 ((1u<<4)|(1u<<7)|(1u<<10)|(16u<<17)|(8u<<24))
__device__ __forceinline__ uint64_t mkdesc(uint32_t addr) {
    return ((uint64_t)2 << 61) | ((uint64_t)1 << 46) | ((uint64_t)64 << 32) | ((uint64_t)1 << 16)
         | ((uint64_t)(addr >> 4) & 0x3FFF);
}
#if HAS_TC
__device__ __forceinline__ void mma_ss(uint32_t d, uint64_t ad, uint64_t bd, uint32_t en) {
    asm volatile("{\n\t.reg .pred p;\n\tsetp.ne.u32 p, %4, 0;\n\t"
        "tcgen05.mma.cta_group::1.kind::f16 [%0], %1, %2, %3, {%5,%5,%5,%5}, p;\n\t}"
        :: "r"(d), "l"(ad), "l"(bd), "r"(IDESC_F16), "r"(en), "r"(0u) : "memory");
}
__device__ __forceinline__ void mma_tile3(uint32_t d, uint32_t a_addr, uint32_t b_addr,
                                          uint32_t mbar, bool fresh, bool commit) {
    if (elect1()) {
        uint64_t adb = mkdesc(a_addr), bdb = mkdesc(b_addr);
#pragma unroll
        for (int t = 0; t < 3; t++) {
            uint64_t ao = adb + (t == 2 ? 2048 : 0);
            uint64_t bo = bdb + (t == 1 ? 2048 : 0);
#pragma unroll
            for (int s = 0; s < 8; s++) {
                uint64_t off = (uint64_t)((s >> 2) * 1024 + (s & 3) * 2);
                mma_ss(d, ao + off, bo + off, (t == 0 && s == 0 && fresh) ? 0u : 1u);
            }
        }
        if (commit)
            asm volatile("tcgen05.commit.cta_group::1.mbarrier::arrive::one.shared::cluster.b64 [%0];"
                         :: "r"(mbar) : "memory");
    }
}
#define MBAR_INIT(a, c) asm volatile("mbarrier.init.shared.b64 [%0], %1;" :: "r"(a), "r"(c) : "memory")
#define MBAR_INVAL(a)   asm volatile("mbarrier.inval.shared.b64 [%0];" :: "r"(a) : "memory")
#define MBAR_WAIT(a, par) do { uint32_t _m=(a), _p=(par); \
    asm volatile("{\n\t.reg .pred P1;\n\tWL%=:\n\t" \
        "mbarrier.try_wait.parity.acquire.cta.shared::cta.b64 P1, [%0], %1, 0x989680;\n\t" \
        "@P1 bra.uni WD%=;\n\tbra.uni WL%=;\n\tWD%=:\n\t}" :: "r"(_m), "r"(_p) : "memory"); } while(0)
#define TC_ALLOC(a, n)   asm volatile("tcgen05.alloc.cta_group::1.sync.aligned.shared::cta.b32 [%0], %1;" :: "r"(a), "r"(n) : "memory")
#define TC_DEALLOC(t, n) asm volatile("tcgen05.dealloc.cta_group::1.sync.aligned.b32 %0, %1;" :: "r"(t), "r"(n))
#define TC_FENCE_AFTER()  asm volatile("tcgen05.fence::after_thread_sync;" ::: "memory")
#define TC_FENCE_BEFORE() asm volatile("tcgen05.fence::before_thread_sync;" ::: "memory")
#define FENCE_ASYNC()    asm volatile("fence.proxy.async.shared::cta;" ::: "memory")
#define TC_WAIT_LD()     asm volatile("tcgen05.wait::ld.sync.aligned;" ::: "memory")
#define CLUSTER_ARRIVE() asm volatile("barrier.cluster.arrive.aligned;" ::: "memory")
#define CLUSTER_WAIT()   asm volatile("barrier.cluster.wait.aligned;" ::: "memory")
#define LDTM32(r, addr) \
    asm volatile("tcgen05.ld.sync.aligned.32x32b.x32.b32 " \
        "{%0,%1,%2,%3,%4,%5,%6,%7,%8,%9,%10,%11,%12,%13,%14,%15," \
        "%16,%17,%18,%19,%20,%21,%22,%23,%24,%25,%26,%27,%28,%29,%30,%31}, [%32];" \
        : "=r"((r)[0]),"=r"((r)[1]),"=r"((r)[2]),"=r"((r)[3]),"=r"((r)[4]),"=r"((r)[5]),"=r"((r)[6]),"=r"((r)[7]), \
          "=r"((r)[8]),"=r"((r)[9]),"=r"((r)[10]),"=r"((r)[11]),"=r"((r)[12]),"=r"((r)[13]),"=r"((r)[14]),"=r"((r)[15]), \
          "=r"((r)[16]),"=r"((r)[17]),"=r"((r)[18]),"=r"((r)[19]),"=r"((r)[20]),"=r"((r)[21]),"=r"((r)[22]),"=r"((r)[23]), \
          "=r"((r)[24]),"=r"((r)[25]),"=r"((r)[26]),"=r"((r)[27]),"=r"((r)[28]),"=r"((r)[29]),"=r"((r)[30]),"=r"((r)[31]) \
        : "r"(addr))
#endif

// smem: S1 64KB | S2 64KB | S3/stage 67584 | aux 4KB
#define STAGE_OFF 131072
#define AUX_OFF   (131072 + 128 * TS * 4)
#define SMEMSZ    (AUX_OFF + 4096)

// ==== k_proj: grid 128, cluster(2). rank0: Q+V+G+gate+VgT; rank1: K + (DSMEM VgT) + U ====
__global__ void __launch_bounds__(512) __cluster_dims__(2, 1, 1)
k_proj(const float* __restrict__ tokens,
       const float* __restrict__ Wq, const float* __restrict__ Wk,
       const float* __restrict__ Wv, const float* __restrict__ Wg,
       const float* __restrict__ bg,
       const float* __restrict__ g1, const float* __restrict__ b1) {
#if HAS_TC
    extern __shared__ __align__(1024) char smem[];
    uint32_t* S1 = (uint32_t*)smem;
    uint32_t* S2 = (uint32_t*)(smem + 65536);
    uint32_t* S3 = (uint32_t*)(smem + STAGE_OFF);
    float* stage = (float*)(smem + STAGE_OFF);
    char* aux = smem + AUX_OFF;
    uint32_t auxa = smem_u32(aux), mA = auxa + 8, mB = auxa + 16;
    float* bgs = (float*)(aux + 32);
    int tid = threadIdx.x, wid = tid >> 5;
    int ci = blockIdx.x >> 1, p = blockIdx.x & 1;

    if (wid == 0) TC_ALLOC(auxa, 512);
    if (tid == 0) { MBAR_INIT(mA, 1); MBAR_INIT(mB, 1); }
    if (p == 0 && tid < 128) bgs[tid] = bg[tid];
    __syncthreads();
    uint32_t tmem;
    asm volatile("ld.shared.b32 %0,[%1];" : "=r"(tmem) : "r"(auxa));
    uint32_t D0 = tmem, D1 = tmem + 128, D2 = tmem + 256;
    uint32_t uS1 = smem_u32(S1), uS2 = smem_u32(S2), uS3 = smem_u32(S3);

    ln512(tokens + (size_t)ci * 16384, stage, g1, b1);
    __syncthreads();
    fill_nt<512>(S1, stage, TS);                 // X pairs
    fill_t<512>(S2, p == 0 ? Wq : Wk, 128);
    __syncthreads();                             // X fp32 fully consumed
    if (p == 0) {
        fill_t<512>(S3, Wv, 128);                // Wv pairs (overwrites stage)
        FENCE_ASYNC();
        __syncthreads();
        if (wid == 0) {
            mma_tile3(D0, uS1, uS2, mA, true, true);     // Q -> mA flip 1
            mma_tile3(D1, uS1, uS3, mB, true, true);     // V -> mB flip 1
        }
        MBAR_WAIT(mA, 0); TC_FENCE_AFTER();              // Q done, S2 free
        fill_t<512>(S2, Wg, 128);
        FENCE_ASYNC(); TC_FENCE_BEFORE();
        __syncthreads();
        if (wid == 0) mma_tile3(D2, uS1, uS2, mA, true, true);   // G -> mA flip 2
        MBAR_WAIT(mB, 0); TC_FENCE_AFTER();              // V done, S3 free
        // Qp epilogue -> pairs -> S3 (overlaps G MMA)
        if (tid < 256) {
            int t = tid & 127, wg = tid >> 7;
            uint32_t rr[2][32];
            LDTM32(rr[0], D0 + (wg * 2 + 0) * 32);
            LDTM32(rr[1], D0 + (wg * 2 + 1) * 32);
            TC_WAIT_LD();
#pragma unroll
            for (int b = 0; b < 2; b++)
#pragma unroll
                for (int j = 0; j < 32; j += 2) {
                    int c = wg * 64 + b * 32 + j;
                    float f0 = phi_f(__uint_as_float(rr[b][j]));
                    float f1 = phi_f(__uint_as_float(rr[b][j + 1]));
                    uint32_t hi, lo; pair2(f0, f1, hi, lo);
                    uint32_t w = bfoff(t, c) >> 2;
                    S3[w] = hi; S3[8192 + w] = lo;
                }
        }
        __syncthreads();
        cp64k<512>(g_QpP + (size_t)ci * 16384, S3);
        MBAR_WAIT(mA, 1); TC_FENCE_AFTER();              // G done
        __syncthreads();
        // gate epilogue: Vg = V * sigmoid(G + bg) -> stage fp32
        if (tid < 256) {
            int t = tid & 127, wg = tid >> 7;
#pragma unroll
            for (int b = 0; b < 2; b++) {
                uint32_t rv[32], rg[32];
                LDTM32(rv, D1 + (wg * 2 + b) * 32);
                LDTM32(rg, D2 + (wg * 2 + b) * 32);
                TC_WAIT_LD();
#pragma unroll
                for (int j = 0; j < 32; j++) {
                    int c = wg * 64 + b * 32 + j;
                    stage[t * TS + c] = __uint_as_float(rv[j]) *
                                        sig_f(__uint_as_float(rg[j]) + bgs[c]);
                }
            }
        }
        __syncthreads();
        fill_t<512>(S1, stage, TS);                      // VgT pairs -> S1
        __syncthreads();
        CLUSTER_ARRIVE();                                // phase 1: VgT ready for peer
        cp64k<512>(g_VgTP + (size_t)ci * 16384, S1);
        CLUSTER_WAIT();
        __syncthreads();
        if (tid == 0) { MBAR_INVAL(mA); MBAR_INVAL(mB); }
        __syncthreads();
        if (wid == 0) TC_DEALLOC(tmem, 512);
        CLUSTER_ARRIVE(); CLUSTER_WAIT();                // phase 2: peer still reads our smem
    } else {
        FENCE_ASYNC();
        __syncthreads();
        if (wid == 0) mma_tile3(D0, uS1, uS2, mA, true, true);  // K -> mA flip 1
        MBAR_WAIT(mA, 0); TC_FENCE_AFTER();
        if (tid < 256) {
            int t = tid & 127, wg = tid >> 7;
            uint32_t rr[2][32];
            LDTM32(rr[0], D0 + (wg * 2 + 0) * 32);
            LDTM32(rr[1], D0 + (wg * 2 + 1) * 32);
            TC_WAIT_LD();
#pragma unroll
            for (int b = 0; b < 2; b++)
#pragma unroll
                for (int j = 0; j < 32; j++)
                    stage[t * TS + wg * 64 + b * 32 + j] = phi_f(__uint_as_float(rr[b][j]));
        }
        __syncthreads();
        fill_nt<512>(g_KpP + (size_t)ci * 16384, stage, TS);   // coalesced gmem
        fill_t<512>(S2, stage, TS);                            // KpT pairs (U operand B)
        if (tid < 128) {
            float s = 0.f;
#pragma unroll 4
            for (int t = 0; t < 128; t++) s += stage[t * TS + tid];
            g_uv[ci * Dm + tid] = s;
        }
        __syncthreads();
        CLUSTER_ARRIVE(); CLUSTER_WAIT();                // phase 1: wait peer VgT
        // DSMEM copy: rank0's S1 (VgT pairs, 64KB) -> own S1
        {
#pragma unroll
            for (int it = 0; it < 8; it++) {
                uint32_t off = (uint32_t)(tid + it * 512) * 16;
                uint32_t src;
                asm volatile("mapa.shared::cluster.u32 %0, %1, %2;"
                             : "=r"(src) : "r"(uS1 + off), "r"(0));
                uint32_t a, b, c, d;
                asm volatile("ld.shared::cluster.v4.b32 {%0,%1,%2,%3}, [%4];"
                             : "=r"(a), "=r"(b), "=r"(c), "=r"(d) : "r"(src));
                *(uint4*)((char*)S1 + off) = make_uint4(a, b, c, d);
            }
        }
        FENCE_ASYNC(); TC_FENCE_BEFORE();
        __syncthreads();
        if (wid == 0) mma_tile3(D0, uS1, uS2, mA, true, true);  // U = VgT@KpT^T -> mA flip 2
        MBAR_WAIT(mA, 1); TC_FENCE_AFTER();
        if (tid < 256) {
            int t = tid & 127, wg = tid >> 7;
            uint32_t rr[2][32];
            LDTM32(rr[0], D0 + (wg * 2 + 0) * 32);
            LDTM32(rr[1], D0 + (wg * 2 + 1) * 32);
            TC_WAIT_LD();
#pragma unroll
            for (int b = 0; b < 2; b++)
#pragma unroll
                for (int j = 0; j < 32; j++)
                    stage[t * TS + wg * 64 + b * 32 + j] = __uint_as_float(rr[b][j]);
        }
        __syncthreads();
        stage_out<512>(g_Ut + (size_t)ci * 16384, stage);
        __syncthreads();
        if (tid == 0) { MBAR_INVAL(mA); MBAR_INVAL(mB); }
        __syncthreads();
        if (wid == 0) TC_DEALLOC(tmem, 512);
        CLUSTER_ARRIVE(); CLUSTER_WAIT();                // phase 2
    }
#endif
}

// ======== k_prefix: scan Ut -> STP pairs (coalesced) + sv; grid 33 ========
__global__ void __launch_bounds__(256) k_prefix() {
    int bid = blockIdx.x, tid = threadIdx.x;
    if (bid < 32) {
        int b = bid >> 4;
        int m = (bid & 15) * 8 + (tid >> 5);
        int lane = tid & 31;
        const float* Ut = g_Ut + (size_t)b * CPB * 16384 + m * 128;
        uint32_t* STP = g_STP + (size_t)b * CPB * 16384;
        uint32_t w0 = bfoff(m, 2 * lane) >> 2;
        uint32_t w1 = bfoff(m, 64 + 2 * lane) >> 2;
        float a0 = 0.f, a1 = 0.f, a2 = 0.f, a3 = 0.f;
#pragma unroll
        for (int c0 = 0; c0 < CPB; c0 += 8) {
            float2 v0[8], v1[8];
#pragma unroll
            for (int j = 0; j < 8; j++) {
                v0[j] = *(const float2*)&Ut[(size_t)(c0 + j) * 16384 + 2 * lane];
                v1[j] = *(const float2*)&Ut[(size_t)(c0 + j) * 16384 + 64 + 2 * lane];
            }
#pragma unroll
            for (int j = 0; j < 8; j++) {
                uint32_t* dst = STP + (size_t)(c0 + j) * 16384;
                uint32_t hi, lo;
                pair2(a0, a1, hi, lo); dst[w0] = hi; dst[8192 + w0] = lo;
                pair2(a2, a3, hi, lo); dst[w1] = hi; dst[8192 + w1] = lo;
                a0 += v0[j].x; a1 += v0[j].y; a2 += v1[j].x; a3 += v1[j].y;
            }
        }
    } else {
        int b = tid >> 7, h = tid & 127;
        float acc = 0.f;
#pragma unroll
        for (int c0 = 0; c0 < CPB; c0 += 8) {
            float v[8];
#pragma unroll
            for (int j = 0; j < 8; j++) v[j] = g_uv[(b * CPB + c0 + j) * Dm + h];
#pragma unroll
            for (int j = 0; j < 8; j++) { g_sv[(b * CPB + c0 + j) * Dm + h] = acc; acc += v[j]; }
        }
    }
}

// ===== k_attn: overlapped chain with 2 mbarriers; grid 64 =====
__global__ void __launch_bounds__(512) k_attn(const float* __restrict__ tokens,
        const float* __restrict__ Wo, const float* __restrict__ g2,
        const float* __restrict__ b2, float* __restrict__ out) {
#if HAS_TC
    extern __shared__ __align__(1024) char smem[];
    uint32_t* S1 = (uint32_t*)smem;
    uint32_t* S2 = (uint32_t*)(smem + 65536);
    uint32_t* S3 = (uint32_t*)(smem + STAGE_OFF);
    float* T = (float*)(smem + STAGE_OFF);
    char* aux = smem + AUX_OFF;
    uint32_t auxa = smem_u32(aux), mA = auxa + 8, mB = auxa + 16;
    float* svs  = (float*)(aux + 32);
    float* denq = (float*)(aux + 544);
    float* denp = (float*)(aux + 1568);
    int tid = threadIdx.x, wid = tid >> 5, ci = blockIdx.x;

    cp64k<512>(S1, g_QpP + (size_t)ci * 16384);
    cp64k<512>(S2, g_KpP + (size_t)ci * 16384);
    cp64k<512>(S3, g_STP + (size_t)ci * 16384);
    if (wid == 0) TC_ALLOC(auxa, 256);
    if (tid == 0) { MBAR_INIT(mA, 1); MBAR_INIT(mB, 1); }
    if (tid < 128) svs[tid] = g_sv[ci * Dm + tid];
    FENCE_ASYNC();
    __syncthreads();
    uint32_t tmem;
    asm volatile("ld.shared.b32 %0,[%1];" : "=r"(tmem) : "r"(auxa));
    uint32_t D0 = tmem, D1 = tmem + 128;
    uint32_t uS1 = smem_u32(S1), uS2 = smem_u32(S2), uS3 = smem_u32(S3);

    if (wid == 0) {
        mma_tile3(D1, uS1, uS2, mA, true, true);      // scores -> mA flip 1
        mma_tile3(D0, uS1, uS3, mB, true, true);      // inter  -> mB flip 1
    }
    MBAR_WAIT(mA, 0); TC_FENCE_AFTER();               // scores done, S2 free
    // threads 0-255: mask epi (D1 -> Amask pairs -> S2); 256-511: denq
    if (tid < 256) {
        int t = tid & 127, wg = tid >> 7;
        float den = 0.f;
        uint32_t r0[32], r1[32];
        LDTM32(r0, D1 + (wg * 2 + 0) * 32);
        LDTM32(r1, D1 + (wg * 2 + 1) * 32);
        TC_WAIT_LD();
#pragma unroll
        for (int b = 0; b < 2; b++) {
            uint32_t* rr = b ? r1 : r0;
#pragma unroll
            for (int j = 0; j < 32; j += 2) {
                int c = wg * 64 + b * 32 + j;
                float f0 = __uint_as_float(rr[j]);     if (c > t)     f0 = 0.f;
                float f1 = __uint_as_float(rr[j + 1]); if (c + 1 > t) f1 = 0.f;
                den += f0 + f1;
                uint32_t hi, lo; pair2(f0, f1, hi, lo);
                uint32_t w = bfoff(t, c) >> 2;
                S2[w] = hi; S2[8192 + w] = lo;
            }
        }
        denp[wg * 128 + t] = den;
    } else {
        int q = tid - 256;
        int t = q & 127, half = q >> 7;
        float den = 0.f;
#pragma unroll 4
        for (int cp = 0; cp < 32; cp++) {
            int col = half * 64 + 2 * cp;
            uint32_t w = bfoff(t, col) >> 2;
            float2 h = unpackbf2(S1[w]);
            float2 l = unpackbf2(S1[8192 + w]);
            den += (h.x + l.x) * svs[col] + (h.y + l.y) * svs[col + 1];
        }
        denq[half * 128 + t] = den;
    }
    __syncthreads();
    MBAR_WAIT(mB, 0); TC_FENCE_AFTER();               // inter done: S1, S3 free
    cp64k<512>(S3, g_VgTP + (size_t)ci * 16384);      // Vg^T pairs
    FENCE_ASYNC(); TC_FENCE_BEFORE();
    __syncthreads();
    if (wid == 0) mma_tile3(D0, uS2, uS3, mA, false, true);   // intra -> mA flip 2
    fill_t<512>(S1, Wo, 128);                         // Wo^T pairs (overlaps intra MMA)
    MBAR_WAIT(mA, 1); TC_FENCE_AFTER();               // intra done: S3 free
    // tokens -> T (overlaps divide epilogue below)
    {
        const float4* t4 = (const float4*)(tokens + (size_t)ci * 16384);
#pragma unroll
        for (int it = 0; it < 8; it++) {
            int p = tid + it * 512;
            int r = p >> 5, c = (p & 31) * 4;
            *(float4*)&T[r * TS + c] = t4[p];
        }
    }
    // divide epilogue -> At pairs -> S2 (Amask dead after intra)
    if (tid < 256) {
        int t = tid & 127, wg = tid >> 7;
        float inv = 1.f / fmaxf(denq[t] + denq[128 + t] + denp[t] + denp[128 + t], ATT_EPS);
        uint32_t r0[32], r1[32];
        LDTM32(r0, D0 + (wg * 2 + 0) * 32);
        LDTM32(r1, D0 + (wg * 2 + 1) * 32);
        TC_WAIT_LD();
#pragma unroll
        for (int b = 0; b < 2; b++) {
            uint32_t* rr = b ? r1 : r0;
#pragma unroll
            for (int j = 0; j < 32; j += 2) {
                int c = wg * 64 + b * 32 + j;
                float f0 = __uint_as_float(rr[j]) * inv;
                float f1 = __uint_as_float(rr[j + 1]) * inv;
                uint32_t hi, lo; pair2(f0, f1, hi, lo);
                uint32_t w = bfoff(t, c) >> 2;
                S2[w] = hi; S2[8192 + w] = lo;
            }
        }
    }
    FENCE_ASYNC(); TC_FENCE_BEFORE();
    __syncthreads();
    if (wid == 0) mma_tile3(D1, uS2, uS1, mB, true, true);    // At @ Wo -> mB flip 2
    MBAR_WAIT(mB, 1); TC_FENCE_AFTER();
    // residual: T += 0.1 * result
    if (tid < 256) {
        int t = tid & 127, wg = tid >> 7;
        uint32_t r0[32], r1[32];
        LDTM32(r0, D1 + (wg * 2 + 0) * 32);
        LDTM32(r1, D1 + (wg * 2 + 1) * 32);
        TC_WAIT_LD();
#pragma unroll
        for (int b = 0; b < 2; b++) {
            uint32_t* rr = b ? r1 : r0;
#pragma unroll
            for (int j = 0; j < 32; j++) {
                int c = wg * 64 + b * 32 + j;
                T[t * TS + c] += 0.1f * __uint_as_float(rr[j]);
            }
        }
    }
    __syncthreads();
    // LN2 -> out
    {
        int lane = tid & 31;
        float4 gg = ((const float4*)g2)[lane], bb = ((const float4*)b2)[lane];
        for (int r = wid; r < 128; r += 16) {
            float4 v = *(const float4*)&T[r * TS + lane * 4];
            float s = v.x + v.y + v.z + v.w;
            float ss = v.x * v.x + v.y * v.y + v.z * v.z + v.w * v.w;
#pragma unroll
            for (int o = 16; o; o >>= 1) {
                s  += __shfl_xor_sync(0xffffffffu, s,  o);
                ss += __shfl_xor_sync(0xffffffffu, ss, o);
            }
            float mu = s * (1.f / 128.f);
            float inv = rsqrtf(ss * (1.f / 128.f) - mu * mu + LN_EPS);
            float4 o4;
            o4.x = (v.x - mu) * inv * gg.x + bb.x;
            o4.y = (v.y - mu) * inv * gg.y + bb.y;
            o4.z = (v.z - mu) * inv * gg.z + bb.z;
            o4.w = (v.w - mu) * inv * gg.w + bb.w;
            *(float4*)&out[((size_t)ci * 128 + r) * 128 + lane * 4] = o4;
        }
    }
    __syncthreads();
    if (tid == 0) { MBAR_INVAL(mA); MBAR_INVAL(mB); }
    __syncthreads();
    if (wid == 0) TC_DEALLOC(tmem, 256);
#endif
}

extern "C" void kernel_launch(void* const* d_in, const int* in_sizes, int n_in,
                              void* d_out, int out_size) {
    const float* tokens = (const float*)d_in[0];
    const float* Wq = (const float*)d_in[1];
    const float* Wk = (const float*)d_in[2];
    const float* Wv = (const float*)d_in[3];
    const float* Wg = (const float*)d_in[4];
    const float* bg = (const float*)d_in[5];
    const float* Wo = (const float*)d_in[6];
    const float* g1 = (const float*)d_in[7];
    const float* b1 = (const float*)d_in[8];
    const float* g2 = (const float*)d_in[9];
    const float* b2 = (const float*)d_in[10];
    float* out = (float*)d_out;

    cudaFuncSetAttribute(k_proj, cudaFuncAttributeMaxDynamicSharedMemorySize, SMEMSZ);
    cudaFuncSetAttribute(k_attn, cudaFuncAttributeMaxDynamicSharedMemorySize, SMEMSZ);

    k_proj<<<128, 512, SMEMSZ>>>(tokens, Wq, Wk, Wv, Wg, bg, g1, b1);
    k_prefix<<<33, 256>>>();
    k_attn<<<64, 512, SMEMSZ>>>(tokens, Wo, g2, b2, out);
}